// round 9
// baseline (speedup 1.0000x reference)
#include <cuda_runtime.h>
#include <cuda_bf16.h>
#include <math.h>
#include <cstdint>

// ---------------------------------------------------------------------------
// MultiWaveletCross on GB300 — round 9: bf16x3 GEMMs + fused shallow pyramid
// + single-launch deep pyramid (Lh<=32) + single-launch deep recon
// ---------------------------------------------------------------------------

#define BB 16
#define CKD 512
#define NTOK 16384

__device__ float g_QA[8388608];
__device__ float g_QB[8388608];
__device__ float g_KA[8388608];
__device__ float g_KB[8388608];
__device__ float g_DQ[4194304];
__device__ float g_DK[4194304];
__device__ float g_US[8380416];
__device__ float g_UD[8380416];
__device__ float g_VA[8388608];
__device__ float g_VB[8388608];
__device__ float2 g_QFs[131072];
__device__ float2 g_KFs[131072];
__device__ float2 g_QFd[131072];
__device__ float2 g_KFd[131072];
__device__ float2 g_OFs[131072];
__device__ float2 g_OFd[131072];
// bf16 split scratch
__device__ __nv_bfloat16 g_Ah[8388608];
__device__ __nv_bfloat16 g_Al[8388608];
__device__ __nv_bfloat16 g_Ah2[8388608];
__device__ __nv_bfloat16 g_Al2[8388608];
__device__ __nv_bfloat16 g_Wh0[262144];
__device__ __nv_bfloat16 g_Wl0[262144];
__device__ __nv_bfloat16 g_Wh1[262144];
__device__ __nv_bfloat16 g_Wl1[262144];
__device__ __nv_bfloat16 g_Wh2[262144];
__device__ __nv_bfloat16 g_Wl2[262144];

__device__ __forceinline__ uint32_t smem_to_u32(const void* p) {
    uint32_t a;
    asm("{ .reg .u64 t; cvta.to.shared.u64 t, %1; cvt.u32.u64 %0, t; }"
        : "=r"(a) : "l"(p));
    return a;
}

// complex tanh (saturating, matches XLA within fp32 noise)
__device__ __forceinline__ float2 ctanh2(float re, float im) {
    float X = 2.f * re, Y = 2.f * im, orr, oii;
    if (fabsf(X) > 20.f) {
        orr = copysignf(1.f, X); oii = 0.f;
    } else {
        float ex = expf(X), enx = 1.f / ex;
        float sh = 0.5f * (ex - enx), ch = 0.5f * (ex + enx);
        float sy, cy; sincosf(Y, &sy, &cy);
        float den = ch + cy;
        orr = sh / den; oii = sy / den;
    }
    return make_float2(orr, oii);
}

// ---------------------------------------------------------------------------
// split kernels
// ---------------------------------------------------------------------------
__device__ __forceinline__ void split_store4(
    __nv_bfloat16* h, __nv_bfloat16* l, long i, float4 v)
{
    __nv_bfloat16 h0 = __float2bfloat16(v.x);
    __nv_bfloat16 h1 = __float2bfloat16(v.y);
    __nv_bfloat16 h2 = __float2bfloat16(v.z);
    __nv_bfloat16 h3 = __float2bfloat16(v.w);
    __nv_bfloat16 l0 = __float2bfloat16(v.x - __bfloat162float(h0));
    __nv_bfloat16 l1 = __float2bfloat16(v.y - __bfloat162float(h1));
    __nv_bfloat16 l2 = __float2bfloat16(v.z - __bfloat162float(h2));
    __nv_bfloat16 l3 = __float2bfloat16(v.w - __bfloat162float(h3));
    __nv_bfloat162* hp = (__nv_bfloat162*)(h + i * 4);
    __nv_bfloat162* lp = (__nv_bfloat162*)(l + i * 4);
    hp[0] = __nv_bfloat162(h0, h1); hp[1] = __nv_bfloat162(h2, h3);
    lp[0] = __nv_bfloat162(l0, l1); lp[1] = __nv_bfloat162(l2, l3);
}

__global__ __launch_bounds__(256) void split_a2_kernel(
    const float* __restrict__ x0, const float* __restrict__ x1,
    __nv_bfloat16* __restrict__ h0, __nv_bfloat16* __restrict__ l0,
    __nv_bfloat16* __restrict__ h1, __nv_bfloat16* __restrict__ l1,
    long n4)
{
    long i = (long)blockIdx.x * 256 + threadIdx.x;
    if (i >= n4) return;
    const float* x = blockIdx.y ? x1 : x0;
    __nv_bfloat16* h = blockIdx.y ? h1 : h0;
    __nv_bfloat16* l = blockIdx.y ? l1 : l0;
    split_store4(h, l, i, *(const float4*)(x + i * 4));
}

__global__ __launch_bounds__(256) void split_wt3_kernel(
    const float* __restrict__ W0, const float* __restrict__ W1,
    const float* __restrict__ W2,
    __nv_bfloat16* __restrict__ h0, __nv_bfloat16* __restrict__ l0,
    __nv_bfloat16* __restrict__ h1, __nv_bfloat16* __restrict__ l1,
    __nv_bfloat16* __restrict__ h2, __nv_bfloat16* __restrict__ l2)
{
    __shared__ float t[32][33];
    int tx = threadIdx.x, ty = threadIdx.y;
    int bx = blockIdx.x, by = blockIdx.y, bz = blockIdx.z;
    const float* W = bz == 0 ? W0 : (bz == 1 ? W1 : W2);
    __nv_bfloat16* hT = bz == 0 ? h0 : (bz == 1 ? h1 : h2);
    __nv_bfloat16* lT = bz == 0 ? l0 : (bz == 1 ? l1 : l2);
#pragma unroll
    for (int j = 0; j < 4; j++)
        t[ty + 8 * j][tx] = W[(size_t)(by * 32 + ty + 8 * j) * 512 + bx * 32 + tx];
    __syncthreads();
#pragma unroll
    for (int j = 0; j < 4; j++) {
        float v = t[tx][ty + 8 * j];
        int n_o = bx * 32 + ty + 8 * j;
        int k_o = by * 32 + tx;
        __nv_bfloat16 hb = __float2bfloat16(v);
        __nv_bfloat16 lb = __float2bfloat16(v - __bfloat162float(hb));
        hT[(size_t)n_o * 512 + k_o] = hb;
        lT[(size_t)n_o * 512 + k_o] = lb;
    }
}

// ---------------------------------------------------------------------------
// bf16x3 GEMM core
// ---------------------------------------------------------------------------
#define LDAE 40
#define ARR_B (128 * LDAE * 2)
#define BUF_B (4 * ARR_B)
#define GSMEM_BYTES (2 * BUF_B)

#define CP_ASYNC16(dst, src) \
    asm volatile("cp.async.cg.shared.global [%0], [%1], 16;" \
        :: "r"(dst), "l"(src))
#define CP_COMMIT() asm volatile("cp.async.commit_group;" ::: "memory")
#define CP_WAIT1() asm volatile("cp.async.wait_group 1;" ::: "memory")
#define CP_WAIT0() asm volatile("cp.async.wait_group 0;" ::: "memory")

#define LDSM_X4(R, addr) \
    asm volatile("ldmatrix.sync.aligned.m8n8.x4.shared.b16 {%0,%1,%2,%3}, [%4];" \
        : "=r"((R)[0]), "=r"((R)[1]), "=r"((R)[2]), "=r"((R)[3]) : "r"(addr))
#define LDSM_X2(R, addr) \
    asm volatile("ldmatrix.sync.aligned.m8n8.x2.shared.b16 {%0,%1}, [%2];" \
        : "=r"((R)[0]), "=r"((R)[1]) : "r"(addr))

#define MMA_BF16(ACC, A, B0, B1) \
    asm volatile( \
        "mma.sync.aligned.m16n8k16.row.col.f32.bf16.bf16.f32 " \
        "{%0,%1,%2,%3}, {%4,%5,%6,%7}, {%8,%9}, {%0,%1,%2,%3};" \
        : "+f"((ACC)[0]), "+f"((ACC)[1]), "+f"((ACC)[2]), "+f"((ACC)[3]) \
        : "r"((A)[0]), "r"((A)[1]), "r"((A)[2]), "r"((A)[3]), \
          "r"(B0), "r"(B1))

__device__ __forceinline__ void gemm_core(
    char* dsm,
    const __nv_bfloat16* __restrict__ Ah, const __nv_bfloat16* __restrict__ Al,
    const __nv_bfloat16* __restrict__ Bh, const __nv_bfloat16* __restrict__ Bl,
    const float* __restrict__ bias, float* __restrict__ C)
{
    const int tid = threadIdx.x;
    const int wid = tid >> 5, lane = tid & 31;
    const int bm = blockIdx.y * 128, bn = blockIdx.x * 128;
    const int wm = (wid >> 2) * 64, wn = (wid & 3) * 32;
    const int lr = lane >> 2, lc = lane & 3;
    const uint32_t sb = smem_to_u32(dsm);

    float acc[4][4][4];
#pragma unroll
    for (int mi = 0; mi < 4; mi++)
#pragma unroll
        for (int ni = 0; ni < 4; ni++)
#pragma unroll
            for (int r = 0; r < 4; r++) acc[mi][ni][r] = 0.f;

    const __nv_bfloat16* gsrc0 = Ah + (size_t)bm * 512;
    const __nv_bfloat16* gsrc1 = Al + (size_t)bm * 512;
    const __nv_bfloat16* gsrc2 = Bh + (size_t)bn * 512;
    const __nv_bfloat16* gsrc3 = Bl + (size_t)bn * 512;

    const int pc0 = tid, pc1 = tid + 256;
    const int pr0 = pc0 >> 2, po0 = (pc0 & 3);
    const int pr1 = pc1 >> 2, po1 = (pc1 & 3);

#define PRODUCE(KB, BUF) do {                                                  \
    uint32_t base = sb + (BUF) * BUF_B;                                        \
    int kg = (KB) * 32;                                                        \
    CP_ASYNC16(base + pr0 * 80 + po0 * 16,                                     \
               gsrc0 + (size_t)pr0 * 512 + kg + po0 * 8);                      \
    CP_ASYNC16(base + pr1 * 80 + po1 * 16,                                     \
               gsrc0 + (size_t)pr1 * 512 + kg + po1 * 8);                      \
    CP_ASYNC16(base + ARR_B + pr0 * 80 + po0 * 16,                             \
               gsrc1 + (size_t)pr0 * 512 + kg + po0 * 8);                      \
    CP_ASYNC16(base + ARR_B + pr1 * 80 + po1 * 16,                             \
               gsrc1 + (size_t)pr1 * 512 + kg + po1 * 8);                      \
    CP_ASYNC16(base + 2 * ARR_B + pr0 * 80 + po0 * 16,                         \
               gsrc2 + (size_t)pr0 * 512 + kg + po0 * 8);                      \
    CP_ASYNC16(base + 2 * ARR_B + pr1 * 80 + po1 * 16,                         \
               gsrc2 + (size_t)pr1 * 512 + kg + po1 * 8);                      \
    CP_ASYNC16(base + 3 * ARR_B + pr0 * 80 + po0 * 16,                         \
               gsrc3 + (size_t)pr0 * 512 + kg + po0 * 8);                      \
    CP_ASYNC16(base + 3 * ARR_B + pr1 * 80 + po1 * 16,                         \
               gsrc3 + (size_t)pr1 * 512 + kg + po1 * 8);                      \
    CP_COMMIT();                                                               \
} while (0)

    const int a_row_off = (lane & 7) + ((lane >> 3) & 1) * 8;
    const int a_k_off = (lane >> 4) * 8;
    const int b_row_off = lane & 7;
    const int b_k_off = ((lane >> 3) & 1) * 8;

    PRODUCE(0, 0);
    for (int kb = 0; kb < 16; kb++) {
        if (kb < 15) PRODUCE(kb + 1, (kb + 1) & 1);
        if (kb < 15) { CP_WAIT1(); } else { CP_WAIT0(); }
        __syncthreads();
        const uint32_t base = sb + (kb & 1) * BUF_B;

#pragma unroll
        for (int k16 = 0; k16 < 32; k16 += 16) {
            uint32_t ah[4][4], al[4][4], bh[4][2], bl[4][2];
#pragma unroll
            for (int mi = 0; mi < 4; mi++) {
                uint32_t addr = base +
                    ((wm + mi * 16 + a_row_off) * LDAE + k16 + a_k_off) * 2;
                LDSM_X4(ah[mi], addr);
                LDSM_X4(al[mi], addr + ARR_B);
            }
#pragma unroll
            for (int ni = 0; ni < 4; ni++) {
                uint32_t addr = base + 2 * ARR_B +
                    ((wn + ni * 8 + b_row_off) * LDAE + k16 + b_k_off) * 2;
                LDSM_X2(bh[ni], addr);
                LDSM_X2(bl[ni], addr + ARR_B);
            }
#pragma unroll
            for (int mi = 0; mi < 4; mi++)
#pragma unroll
                for (int ni = 0; ni < 4; ni++) {
                    MMA_BF16(acc[mi][ni], ah[mi], bh[ni][0], bh[ni][1]);
                    MMA_BF16(acc[mi][ni], ah[mi], bl[ni][0], bl[ni][1]);
                    MMA_BF16(acc[mi][ni], al[mi], bh[ni][0], bh[ni][1]);
                }
        }
        __syncthreads();
    }

#pragma unroll
    for (int mi = 0; mi < 4; mi++) {
#pragma unroll
        for (int ni = 0; ni < 4; ni++) {
            int col = bn + wn + ni * 8 + 2 * lc;
            float2 bv = *(const float2*)(bias + col);
            int r0 = bm + wm + mi * 16 + lr;
            float2 o0 = make_float2(acc[mi][ni][0] + bv.x, acc[mi][ni][1] + bv.y);
            float2 o1 = make_float2(acc[mi][ni][2] + bv.x, acc[mi][ni][3] + bv.y);
            *(float2*)(C + (size_t)r0 * 512 + col) = o0;
            *(float2*)(C + (size_t)(r0 + 8) * 512 + col) = o1;
        }
    }
#undef PRODUCE
}

__global__ __launch_bounds__(256) void gemm_bf16x3(
    const __nv_bfloat16* __restrict__ Ah, const __nv_bfloat16* __restrict__ Al,
    const __nv_bfloat16* __restrict__ Bh, const __nv_bfloat16* __restrict__ Bl,
    const float* __restrict__ bias, float* __restrict__ C)
{
    extern __shared__ __align__(16) char dsm[];
    gemm_core(dsm, Ah, Al, Bh, Bl, bias, C);
}

__global__ __launch_bounds__(256) void gemm_bf16x3_dual(
    const __nv_bfloat16* __restrict__ Ah0, const __nv_bfloat16* __restrict__ Al0,
    const __nv_bfloat16* __restrict__ Bh0, const __nv_bfloat16* __restrict__ Bl0,
    const float* __restrict__ b0, float* __restrict__ C0,
    const __nv_bfloat16* __restrict__ Ah1, const __nv_bfloat16* __restrict__ Al1,
    const __nv_bfloat16* __restrict__ Bh1, const __nv_bfloat16* __restrict__ Bl1,
    const float* __restrict__ b1, float* __restrict__ C1)
{
    extern __shared__ __align__(16) char dsm[];
    if (blockIdx.z == 0)
        gemm_core(dsm, Ah0, Al0, Bh0, Bl0, b0, C0);
    else
        gemm_core(dsm, Ah1, Al1, Bh1, Bl1, b1, C1);
}

// ---------------------------------------------------------------------------
// Wavelet step — q and k in one launch (shallow levels)
// ---------------------------------------------------------------------------
__global__ __launch_bounds__(256) void wavelet2_kernel(
    const float* __restrict__ xq, const float* __restrict__ xk,
    const float* __restrict__ ecd, const float* __restrict__ ecs,
    float* __restrict__ dq, float* __restrict__ qn,
    float* __restrict__ dk, float* __restrict__ kn, int Lh)
{
    __shared__ float wd[16][8], ws_[16][8];
    int tid = threadIdx.x;
    if (tid < 128)       wd[tid >> 3][tid & 7] = ecd[tid];
    else if (tid < 256)  { int t = tid - 128; ws_[t >> 3][t & 7] = ecs[t]; }
    __syncthreads();

    const float* x = blockIdx.y ? xk : xq;
    float* od = blockIdx.y ? dk : dq;
    float* os = blockIdx.y ? kn : qn;

    long idx = (long)blockIdx.x * 256 + tid;
    long total = (long)BB * Lh * 64;
    if (idx >= total) return;
    int c = (int)(idx & 63);
    long bt = idx >> 6;
    int t2 = (int)(bt % Lh);
    int b = (int)(bt / Lh);

    const float* p0 = x + ((long)(b * 2 * Lh + 2 * t2)) * CKD + c * 8;
    float a[16];
    *(float4*)(a)      = *(const float4*)(p0);
    *(float4*)(a + 4)  = *(const float4*)(p0 + 4);
    *(float4*)(a + 8)  = *(const float4*)(p0 + CKD);
    *(float4*)(a + 12) = *(const float4*)(p0 + CKD + 4);

    float rd[8], rs[8];
#pragma unroll
    for (int kk = 0; kk < 8; kk++) { rd[kk] = 0.f; rs[kk] = 0.f; }
#pragma unroll
    for (int j = 0; j < 16; j++)
#pragma unroll
        for (int kk = 0; kk < 8; kk++) {
            rd[kk] += a[j] * wd[j][kk];
            rs[kk] += a[j] * ws_[j][kk];
        }
    float* pd = od + ((long)(b * Lh + t2)) * CKD + c * 8;
    float* ps = os + ((long)(b * Lh + t2)) * CKD + c * 8;
    *(float4*)(pd)     = *(float4*)(rd);
    *(float4*)(pd + 4) = *(float4*)(rd + 4);
    *(float4*)(ps)     = *(float4*)(rs);
    *(float4*)(ps + 4) = *(float4*)(rs + 4);
}

// ---------------------------------------------------------------------------
// Reconstruction step (shallow; optionally emits bf16 hi/lo split)
// ---------------------------------------------------------------------------
__global__ __launch_bounds__(256) void recon_kernel(
    const float* __restrict__ vin, const float* __restrict__ us,
    const float* __restrict__ ud, const float* __restrict__ rce,
    const float* __restrict__ rco, float* __restrict__ vout, int Lv,
    __nv_bfloat16* __restrict__ oh, __nv_bfloat16* __restrict__ ol,
    int do_split)
{
    __shared__ float we[16][8], wo[16][8];
    int tid = threadIdx.x;
    if (tid < 128)       we[tid >> 3][tid & 7] = rce[tid];
    else if (tid < 256)  { int t = tid - 128; wo[t >> 3][t & 7] = rco[t]; }
    __syncthreads();

    long idx = (long)blockIdx.x * 256 + tid;
    long total = (long)BB * Lv * 64;
    if (idx >= total) return;
    int c = (int)(idx & 63);
    long bt = idx >> 6;
    int t = (int)(bt % Lv);
    int b = (int)(bt / Lv);

    long base = ((long)(b * Lv + t)) * CKD + c * 8;
    float a[16];
#pragma unroll
    for (int j = 0; j < 8; j++) a[j] = vin[base + j] + us[base + j];
    *(float4*)(a + 8)  = *(const float4*)(ud + base);
    *(float4*)(a + 12) = *(const float4*)(ud + base + 4);

    float re[8], ro[8];
#pragma unroll
    for (int kk = 0; kk < 8; kk++) { re[kk] = 0.f; ro[kk] = 0.f; }
#pragma unroll
    for (int j = 0; j < 16; j++)
#pragma unroll
        for (int kk = 0; kk < 8; kk++) {
            re[kk] += a[j] * we[j][kk];
            ro[kk] += a[j] * wo[j][kk];
        }
    long obase = ((long)(b * 2 * Lv + 2 * t)) * CKD + c * 8;
    float* pe = vout + obase;
    *(float4*)(pe)           = *(float4*)(re);
    *(float4*)(pe + 4)       = *(float4*)(re + 4);
    *(float4*)(pe + CKD)     = *(float4*)(ro);
    *(float4*)(pe + CKD + 4) = *(float4*)(ro + 4);

    if (do_split) {
        split_store4(oh, ol, (obase >> 2),           *(float4*)(re));
        split_store4(oh, ol, (obase >> 2) + 1,       *(float4*)(re + 4));
        split_store4(oh, ol, ((obase + CKD) >> 2),     *(float4*)(ro));
        split_store4(oh, ol, ((obase + CKD) >> 2) + 1, *(float4*)(ro + 4));
    }
}

// ---------------------------------------------------------------------------
// rfft x4 streams (shallow levels)
// ---------------------------------------------------------------------------
__global__ __launch_bounds__(256) void rfft4_kernel(
    const float* __restrict__ s0, const float* __restrict__ s1,
    const float* __restrict__ s2, const float* __restrict__ s3,
    float2* __restrict__ F0, float2* __restrict__ F1,
    float2* __restrict__ F2, float2* __restrict__ F3,
    int L, int m)
{
    __shared__ float twc[512], tws[512];
    __shared__ float tile[64][64];
    int tid = threadIdx.x;
    int ec = blockIdx.x;
    int b = blockIdx.y;
    int z = blockIdx.z;
    const float* x = z == 0 ? s0 : (z == 1 ? s1 : (z == 2 ? s2 : s3));
    float2* F = z == 0 ? F0 : (z == 1 ? F1 : (z == 2 ? F2 : F3));

    for (int i = tid; i < L; i += 256) {
        float th = 6.2831853071795864f * (float)i / (float)L;
        float s, c; sincosf(th, &s, &c);
        twc[i] = c; tws[i] = s;
    }

    int eh = tid >> 2;
    int xg = tid & 3;
    float ar[4] = {0.f, 0.f, 0.f, 0.f}, ai[4] = {0.f, 0.f, 0.f, 0.f};

    for (int t0 = 0; t0 < L; t0 += 64) {
        int tc = L - t0 < 64 ? L - t0 : 64;
        __syncthreads();
        for (int i = tid; i < tc * 64; i += 256) {
            int tt = i >> 6, el = i & 63;
            tile[tt][el] = x[((long)(b * L + t0 + tt)) * CKD + ec * 64 + el];
        }
        __syncthreads();
        for (int tt = 0; tt < tc; tt++) {
            float v = tile[tt][eh];
            int t = t0 + tt;
#pragma unroll
            for (int j = 0; j < 4; j++) {
                int xx = xg + j * 4;
                int id = (xx * t) & (L - 1);
                ar[j] += v * twc[id];
                ai[j] -= v * tws[id];
            }
        }
    }
    int e = ec * 8 + (eh >> 3), h = eh & 7;
    float2* dst = F + ((long)((b * 8 + h) * 64 + e)) * 16;
#pragma unroll
    for (int j = 0; j < 4; j++) {
        int xx = xg + j * 4;
        if (xx < m) dst[xx] = make_float2(ar[j], ai[j]);
    }
}

// ---------------------------------------------------------------------------
// attn x2 pairs (shallow levels)
// ---------------------------------------------------------------------------
__global__ __launch_bounds__(256) void attn2_kernel(
    const float2* __restrict__ QFs, const float2* __restrict__ KFs,
    float2* __restrict__ OFs,
    const float2* __restrict__ QFd, const float2* __restrict__ KFd,
    float2* __restrict__ OFd, int m)
{
    __shared__ float2 qf[1024], kf[1024], S[256];
    int bh = blockIdx.x & 127, pair = blockIdx.x >> 7;
    int tid = threadIdx.x;
    const float2* QF = pair ? QFd : QFs;
    const float2* KF = pair ? KFd : KFs;
    float2* OF = pair ? OFd : OFs;
    const float2* qsrc = QF + (long)bh * 1024;
    const float2* ksrc = KF + (long)bh * 1024;
    for (int i = tid; i < 1024; i += 256) { qf[i] = qsrc[i]; kf[i] = ksrc[i]; }
    __syncthreads();

    for (int s = tid; s < m * m; s += 256) {
        int xx = s / m, yy = s - xx * m;
        float re = 0.f, im = 0.f;
#pragma unroll 8
        for (int e = 0; e < 64; e++) {
            float2 qv = qf[e * 16 + xx], kv = kf[e * 16 + yy];
            re += qv.x * kv.x - qv.y * kv.y;
            im += qv.x * kv.y + qv.y * kv.x;
        }
        S[xx * 16 + yy] = ctanh2(re, im);
    }
    __syncthreads();
    for (int o = tid; o < 64 * m; o += 256) {
        int e = o / m, xx = o - e * m;
        float re = 0.f, im = 0.f;
        for (int yy = 0; yy < m; yy++) {
            float2 sv = S[xx * 16 + yy], kv = kf[e * 16 + yy];
            re += sv.x * kv.x - sv.y * kv.y;
            im += sv.x * kv.y + sv.y * kv.x;
        }
        OF[(long)bh * 1024 + e * 16 + xx] = make_float2(re, im);
    }
}

// ---------------------------------------------------------------------------
// irfft x2 (shallow levels)
// ---------------------------------------------------------------------------
__global__ __launch_bounds__(256) void irfft2_kernel(
    const float2* __restrict__ OFs, const float2* __restrict__ OFd,
    float* __restrict__ US, float* __restrict__ UD, int L, int m)
{
    __shared__ float twc[512], tws[512];
    __shared__ float2 of_s[64][16];
    int tid = threadIdx.x, ec = blockIdx.x, b = blockIdx.y, z = blockIdx.z;
    float* out = z ? UD : US;

    for (int i = tid; i < L; i += 256) {
        float th = 6.2831853071795864f * (float)i / (float)L;
        float s, c; sincosf(th, &s, &c);
        twc[i] = c; tws[i] = s;
    }
    float inv = 1.f / ((float)L * 4096.f);
    for (int i = tid; i < 1024; i += 256) {
        int el = i >> 4, xx = i & 15;
        int e = ec * 8 + (el >> 3), h = el & 7;
        float2 v = make_float2(0.f, 0.f);
        if (xx < m) {
            long src = ((long)((b * 8 + h) * 64 + e)) * 16 + xx;
            v = OFs[src];
            if (z) { float2 d = OFd[src]; v.x += d.x; v.y += d.y; }
        }
        float w = (xx == 0) ? inv : 2.f * inv;
        of_s[el][xx] = make_float2(v.x * w, v.y * w);
    }
    __syncthreads();

    for (long i = tid; i < (long)L * 64; i += 256) {
        int el = (int)(i & 63);
        int t = (int)(i >> 6);
        float acc = 0.f;
#pragma unroll
        for (int xx = 0; xx < 16; xx++) {
            int id = (xx * t) & (L - 1);
            float2 f = of_s[el][xx];
            acc += f.x * twc[id] - f.y * tws[id];
        }
        long dst = ((long)(b * L + t)) * CKD + ec * 64 + el;
        out[dst] = acc;
    }
}

// ---------------------------------------------------------------------------
// FUSED deep levels (Lh = 32,16,8,4,2,1): one CTA per batch b, all phases
// and all levels in one launch. gmem scratch is CTA-local per b; __syncthreads
// orders global accesses within the CTA.
// ---------------------------------------------------------------------------
__global__ __launch_bounds__(512) void deep_levels_kernel(
    float* __restrict__ q0, float* __restrict__ q1,
    float* __restrict__ k0, float* __restrict__ k1,
    float* __restrict__ DQ, float* __restrict__ DK,
    float2* __restrict__ QFs, float2* __restrict__ KFs,
    float2* __restrict__ QFd, float2* __restrict__ KFd,
    float2* __restrict__ OFs, float2* __restrict__ OFd,
    const float* __restrict__ ecd, const float* __restrict__ ecs,
    float* __restrict__ USb, float* __restrict__ UDb, long off4)
{
    __shared__ float wd[16][8], ws_[16][8];
    __shared__ float twc[32], tws[32];
    __shared__ float2 Ss[2048], Sd[2048];   // [h][x*16+y]
    const int tid = threadIdx.x;
    const int b = blockIdx.x;

    if (tid < 128)       wd[tid >> 3][tid & 7] = ecd[tid];
    else if (tid < 256)  { int t = tid - 128; ws_[t >> 3][t & 7] = ecs[t]; }
    __syncthreads();

    float* qc = q0; float* qn = q1;
    float* kc = k0; float* kn = k1;
    long off = off4;

    for (int j = 0; j < 6; j++) {
        const int Lh = 32 >> j;          // 32,16,8,4,2,1
        float* US = USb + off;
        float* UD = UDb + off;
        off += (long)BB * Lh * CKD;

        if (Lh == 1) {  // m = 0: outputs are zero
            for (int i = tid; i < 512; i += 512) {
                US[(long)b * 512 + i] = 0.f;
                UD[(long)b * 512 + i] = 0.f;
            }
            break;
        }
        const int m = (Lh >> 1) < 16 ? (Lh >> 1) : 16;

        // twiddles (Lh <= 32)
        if (tid < Lh) {
            float th = 6.2831853071795864f * (float)tid / (float)Lh;
            float s, c; sincosf(th, &s, &c);
            twc[tid] = c; tws[tid] = s;
        }
        __syncthreads();

        // ---- wavelet: items 2 * Lh * 64 ----
        {
            int nW = 2 * Lh * 64;
            for (int it = tid; it < nW; it += 512) {
                int z = it >= Lh * 64;
                int r = z ? it - Lh * 64 : it;
                int c = r & 63, t2 = r >> 6;
                const float* x = z ? kc : qc;
                float* od = z ? DK : DQ;
                float* os = z ? kn : qn;
                const float* p0 = x + ((long)(b * 2 * Lh + 2 * t2)) * CKD + c * 8;
                float a[16];
                *(float4*)(a)      = *(const float4*)(p0);
                *(float4*)(a + 4)  = *(const float4*)(p0 + 4);
                *(float4*)(a + 8)  = *(const float4*)(p0 + CKD);
                *(float4*)(a + 12) = *(const float4*)(p0 + CKD + 4);
                float rd[8], rs[8];
#pragma unroll
                for (int kk = 0; kk < 8; kk++) { rd[kk] = 0.f; rs[kk] = 0.f; }
#pragma unroll
                for (int jj = 0; jj < 16; jj++)
#pragma unroll
                    for (int kk = 0; kk < 8; kk++) {
                        rd[kk] += a[jj] * wd[jj][kk];
                        rs[kk] += a[jj] * ws_[jj][kk];
                    }
                float* pd = od + ((long)(b * Lh + t2)) * CKD + c * 8;
                float* ps = os + ((long)(b * Lh + t2)) * CKD + c * 8;
                *(float4*)(pd)     = *(float4*)(rd);
                *(float4*)(pd + 4) = *(float4*)(rd + 4);
                *(float4*)(ps)     = *(float4*)(rs);
                *(float4*)(ps + 4) = *(float4*)(rs + 4);
            }
        }
        __syncthreads();

        // ---- rfft: items 4 * 512 (stream z, channel ch) ----
        {
            for (int it = tid; it < 4 * 512; it += 512) {
                int z = it >> 9;
                int ch = it & 511;
                const float* x = z == 0 ? DQ : (z == 1 ? DK : (z == 2 ? qn : kn));
                float2* F = z == 0 ? QFs : (z == 1 ? KFs : (z == 2 ? QFd : KFd));
                int e = ch >> 3, h = ch & 7;
                float xv[32];
#pragma unroll
                for (int t = 0; t < 32; t++)
                    xv[t] = (t < Lh) ? x[((long)(b * Lh + t)) * CKD + ch] : 0.f;
                float2* dst = F + ((long)((b * 8 + h) * 64 + e)) * 16;
#pragma unroll
                for (int xx = 0; xx < 16; xx++) {
                    if (xx >= m) break;
                    float ar = 0.f, ai = 0.f;
#pragma unroll
                    for (int t = 0; t < 32; t++) {
                        if (t < Lh) {
                            int id = (xx * t) & (Lh - 1);
                            ar += xv[t] * twc[id];
                            ai -= xv[t] * tws[id];
                        }
                    }
                    dst[xx] = make_float2(ar, ai);
                }
            }
        }
        __syncthreads();

        // ---- attn S: items 2 * 8 * m * m ----
        {
            int mm = m * m;
            int nS = 2 * 8 * mm;
            for (int it = tid; it < nS; it += 512) {
                int z = it >= 8 * mm;
                int r = z ? it - 8 * mm : it;
                int h = r / mm; int r2 = r - h * mm;
                int xx = r2 / m, yy = r2 - xx * m;
                const float2* QF = z ? QFd : QFs;
                const float2* KF = z ? KFd : KFs;
                const float2* qrow = QF + ((long)(b * 8 + h) * 64) * 16;
                const float2* krow = KF + ((long)(b * 8 + h) * 64) * 16;
                float re = 0.f, im = 0.f;
#pragma unroll 8
                for (int e = 0; e < 64; e++) {
                    float2 qv = qrow[e * 16 + xx], kv = krow[e * 16 + yy];
                    re += qv.x * kv.x - qv.y * kv.y;
                    im += qv.x * kv.y + qv.y * kv.x;
                }
                (z ? Sd : Ss)[h * 256 + xx * 16 + yy] = ctanh2(re, im);
            }
        }
        __syncthreads();

        // ---- attn OF: items 2 * 8 * 64 * m ----
        {
            int nO = 2 * 8 * 64 * m;
            for (int it = tid; it < nO; it += 512) {
                int z = it >= 8 * 64 * m;
                int r = z ? it - 8 * 64 * m : it;
                int h = r / (64 * m); int r2 = r - h * 64 * m;
                int e = r2 / m, xx = r2 - e * m;
                const float2* KF = z ? KFd : KFs;
                float2* OF = z ? OFd : OFs;
                const float2* krow = KF + ((long)(b * 8 + h) * 64) * 16;
                const float2* Sp = (z ? Sd : Ss) + h * 256 + xx * 16;
                float re = 0.f, im = 0.f;
                for (int yy = 0; yy < m; yy++) {
                    float2 sv = Sp[yy], kv = krow[e * 16 + yy];
                    re += sv.x * kv.x - sv.y * kv.y;
                    im += sv.x * kv.y + sv.y * kv.x;
                }
                OF[((long)(b * 8 + h) * 64 + e) * 16 + xx] = make_float2(re, im);
            }
        }
        __syncthreads();

        // ---- irfft: items 2 * Lh * 512 ----
        {
            float inv = 1.f / ((float)Lh * 4096.f);
            int nI = 2 * Lh * 512;
            for (int it = tid; it < nI; it += 512) {
                int z = it >= Lh * 512;
                int r = z ? it - Lh * 512 : it;
                int ch = r & 511, t = r >> 9;
                int e = ch >> 3, h = ch & 7;
                const float2* ofs = OFs + ((long)(b * 8 + h) * 64 + e) * 16;
                const float2* ofd = OFd + ((long)(b * 8 + h) * 64 + e) * 16;
                float acc = 0.f;
#pragma unroll
                for (int xx = 0; xx < 16; xx++) {
                    if (xx >= m) break;
                    float2 f = ofs[xx];
                    if (z) { float2 d = ofd[xx]; f.x += d.x; f.y += d.y; }
                    float w = (xx == 0) ? inv : 2.f * inv;
                    int id = (xx * t) & (Lh - 1);
                    acc += w * (f.x * twc[id] - f.y * tws[id]);
                }
                (z ? UD : US)[((long)(b * Lh + t)) * CKD + ch] = acc;
            }
        }
        __syncthreads();

        { float* t = qc; qc = qn; qn = t; }
        { float* t = kc; kc = kn; kn = t; }
    }
}

// ---------------------------------------------------------------------------
// FUSED deep recon (Lv = 1..32): one CTA per b, 6 steps in one launch.
// Initial v is implicitly zero. Final v (len 64) lands in v0.
// ---------------------------------------------------------------------------
__global__ __launch_bounds__(512) void deep_recon_kernel(
    const float* __restrict__ USb, const float* __restrict__ UDb,
    const float* __restrict__ rce, const float* __restrict__ rco,
    float* __restrict__ v0, float* __restrict__ v1, long off4)
{
    __shared__ float we[16][8], wo[16][8];
    const int tid = threadIdx.x;
    const int b = blockIdx.x;
    if (tid < 128)       we[tid >> 3][tid & 7] = rce[tid];
    else if (tid < 256)  { int t = tid - 128; wo[t >> 3][t & 7] = rco[t]; }
    __syncthreads();

    long offs[6];
    {
        long off = off4;
        for (int j = 0; j < 6; j++) { offs[j] = off; off += (long)BB * (32 >> j) * CKD; }
    }

    float* vc = v0; float* vn = v1;
    for (int j = 5; j >= 0; j--) {
        int Lv = 32 >> j;
        const float* US = USb + offs[j];
        const float* UD = UDb + offs[j];
        int first = (j == 5);
        int nR = Lv * 64;
        for (int it = tid; it < nR; it += 512) {
            int c = it & 63, t = it >> 6;
            long base = ((long)(b * Lv + t)) * CKD + c * 8;
            float a[16];
#pragma unroll
            for (int jj = 0; jj < 8; jj++)
                a[jj] = (first ? 0.f : vc[base + jj]) + US[base + jj];
            *(float4*)(a + 8)  = *(const float4*)(UD + base);
            *(float4*)(a + 12) = *(const float4*)(UD + base + 4);
            float re[8], ro[8];
#pragma unroll
            for (int kk = 0; kk < 8; kk++) { re[kk] = 0.f; ro[kk] = 0.f; }
#pragma unroll
            for (int jj = 0; jj < 16; jj++)
#pragma unroll
                for (int kk = 0; kk < 8; kk++) {
                    re[kk] += a[jj] * we[jj][kk];
                    ro[kk] += a[jj] * wo[jj][kk];
                }
            long obase = ((long)(b * 2 * Lv + 2 * t)) * CKD + c * 8;
            float* pe = vn + obase;
            *(float4*)(pe)           = *(float4*)(re);
            *(float4*)(pe + 4)       = *(float4*)(re + 4);
            *(float4*)(pe + CKD)     = *(float4*)(ro);
            *(float4*)(pe + CKD + 4) = *(float4*)(ro + 4);
        }
        __syncthreads();
        { float* t = vc; vc = vn; vn = t; }
    }
    // 6 steps: writes go v1,v0,v1,v0,v1,v0 -> final len-64 v is in v0. ✓
}

// ---------------------------------------------------------------------------
extern "C" void kernel_launch(void* const* d_in, const int* in_sizes, int n_in,
                              void* d_out, int out_size)
{
    const float* q    = (const float*)d_in[0];
    const float* k    = (const float*)d_in[1];
    const float* Lq_w = (const float*)d_in[3];
    const float* Lq_b = (const float*)d_in[4];
    const float* Lk_w = (const float*)d_in[5];
    const float* Lk_b = (const float*)d_in[6];
    const float* out_w = (const float*)d_in[9];
    const float* out_b = (const float*)d_in[10];
    const float* ec_s = (const float*)d_in[11];
    const float* ec_d = (const float*)d_in[12];
    const float* rc_e = (const float*)d_in[13];
    const float* rc_o = (const float*)d_in[14];

    float *QA, *QB, *KA, *KB, *DQ, *DK, *US, *UD, *VA, *VB;
    float2 *QFs, *KFs, *QFd, *KFd, *OFs, *OFd;
    __nv_bfloat16 *Ah, *Al, *Ah2, *Al2, *Wh0, *Wl0, *Wh1, *Wl1, *Wh2, *Wl2;
    cudaGetSymbolAddress((void**)&QA, g_QA);
    cudaGetSymbolAddress((void**)&QB, g_QB);
    cudaGetSymbolAddress((void**)&KA, g_KA);
    cudaGetSymbolAddress((void**)&KB, g_KB);
    cudaGetSymbolAddress((void**)&DQ, g_DQ);
    cudaGetSymbolAddress((void**)&DK, g_DK);
    cudaGetSymbolAddress((void**)&US, g_US);
    cudaGetSymbolAddress((void**)&UD, g_UD);
    cudaGetSymbolAddress((void**)&VA, g_VA);
    cudaGetSymbolAddress((void**)&VB, g_VB);
    cudaGetSymbolAddress((void**)&QFs, g_QFs);
    cudaGetSymbolAddress((void**)&KFs, g_KFs);
    cudaGetSymbolAddress((void**)&QFd, g_QFd);
    cudaGetSymbolAddress((void**)&KFd, g_KFd);
    cudaGetSymbolAddress((void**)&OFs, g_OFs);
    cudaGetSymbolAddress((void**)&OFd, g_OFd);
    cudaGetSymbolAddress((void**)&Ah, g_Ah);
    cudaGetSymbolAddress((void**)&Al, g_Al);
    cudaGetSymbolAddress((void**)&Ah2, g_Ah2);
    cudaGetSymbolAddress((void**)&Al2, g_Al2);
    cudaGetSymbolAddress((void**)&Wh0, g_Wh0);
    cudaGetSymbolAddress((void**)&Wl0, g_Wl0);
    cudaGetSymbolAddress((void**)&Wh1, g_Wh1);
    cudaGetSymbolAddress((void**)&Wl1, g_Wl1);
    cudaGetSymbolAddress((void**)&Wh2, g_Wh2);
    cudaGetSymbolAddress((void**)&Wl2, g_Wl2);

    cudaFuncSetAttribute(gemm_bf16x3,
                         cudaFuncAttributeMaxDynamicSharedMemorySize,
                         GSMEM_BYTES);
    cudaFuncSetAttribute(gemm_bf16x3_dual,
                         cudaFuncAttributeMaxDynamicSharedMemorySize,
                         GSMEM_BYTES);

    // weight splits + input splits + dual projection GEMM
    split_wt3_kernel<<<dim3(16, 16, 3), dim3(32, 8)>>>(
        Lq_w, Lk_w, out_w, Wh0, Wl0, Wh1, Wl1, Wh2, Wl2);
    split_a2_kernel<<<dim3(8192, 2), 256>>>(q, k, Ah, Al, Ah2, Al2, 2097152);
    gemm_bf16x3_dual<<<dim3(4, 128, 2), 256, GSMEM_BYTES>>>(
        Ah, Al, Wh0, Wl0, Lq_b, QA,
        Ah2, Al2, Wh1, Wl1, Lk_b, KA);

    // shallow levels (Lh = 512, 256, 128, 64)
    float* qc = QA; float* qn = QB;
    float* kc = KA; float* kn = KB;
    long offs[4];
    long off = 0;
    int L = 1024;
    for (int i = 0; i < 4; i++) {
        int Lh = L >> 1;
        offs[i] = off;
        off += (long)BB * Lh * CKD;
        long total = (long)BB * Lh * 64;
        int blocks = (int)((total + 255) / 256);

        wavelet2_kernel<<<dim3(blocks, 2), 256>>>(
            qc, kc, ec_d, ec_s, DQ, qn, DK, kn, Lh);
        rfft4_kernel<<<dim3(8, BB, 4), 256>>>(
            DQ, DK, qn, kn, QFs, KFs, QFd, KFd, Lh, 16);
        attn2_kernel<<<256, 256>>>(QFs, KFs, OFs, QFd, KFd, OFd, 16);
        irfft2_kernel<<<dim3(8, BB, 2), 256>>>(
            OFs, OFd, US + offs[i], UD + offs[i], Lh, 16);

        { float* t = qc; qc = qn; qn = t; }
        { float* t = kc; kc = kn; kn = t; }
        L = Lh;
    }
    const long off4 = off;   // offset of level 4 (Lh=32) in US/UD

    // fused deep pyramid (Lh = 32 ... 1) — one launch, one CTA per b
    deep_levels_kernel<<<BB, 512>>>(
        qc, qn, kc, kn, DQ, DK,
        QFs, KFs, QFd, KFd, OFs, OFd,
        ec_d, ec_s, US, UD, off4);

    // fused deep recon (Lv = 1 ... 32) — final len-64 v lands in VA
    deep_recon_kernel<<<BB, 512>>>(US, UD, rc_e, rc_o, VA, VB, off4);

    // shallow recon (Lv = 64, 128, 256, 512); last one emits bf16 split
    float* vc = VA; float* vn = VB;
    for (int i = 3; i >= 0; i--) {
        int Lv = 1024 >> (i + 1);
        long total = (long)BB * Lv * 64;
        recon_kernel<<<(int)((total + 255) / 256), 256>>>(
            vc, US + offs[i], UD + offs[i], rc_e, rc_o, vn, Lv,
            Ah, Al, (i == 0) ? 1 : 0);
        float* t = vc; vc = vn; vn = t;
    }

    // output projection (recon emitted the bf16 split into Ah/Al)
    gemm_bf16x3<<<dim3(4, 128), 256, GSMEM_BYTES>>>(
        Ah, Al, Wh2, Wl2, out_b, (float*)d_out);
}

// round 12
// speedup vs baseline: 1.9725x; 1.9725x over previous
#include <cuda_runtime.h>
#include <cuda_bf16.h>
#include <math.h>
#include <cstdint>

// ---------------------------------------------------------------------------
// MultiWaveletCross on GB300 — round 12: round-8 structure (known good)
// + gemm occupancy forced to 2 CTAs/SM  (resubmit of round-10/11 after infra
//   failure; no code change)
// ---------------------------------------------------------------------------

#define BB 16
#define CKD 512
#define NTOK 16384

__device__ float g_QA[8388608];
__device__ float g_QB[8388608];
__device__ float g_KA[8388608];
__device__ float g_KB[8388608];
__device__ float g_DQ[4194304];
__device__ float g_DK[4194304];
__device__ float g_US[8380416];
__device__ float g_UD[8380416];
__device__ float g_VA[8388608];
__device__ float g_VB[8388608];
__device__ float2 g_QFs[131072];
__device__ float2 g_KFs[131072];
__device__ float2 g_QFd[131072];
__device__ float2 g_KFd[131072];
__device__ float2 g_OFs[131072];
__device__ float2 g_OFd[131072];
// bf16 split scratch
__device__ __nv_bfloat16 g_Ah[8388608];
__device__ __nv_bfloat16 g_Al[8388608];
__device__ __nv_bfloat16 g_Ah2[8388608];
__device__ __nv_bfloat16 g_Al2[8388608];
__device__ __nv_bfloat16 g_Wh0[262144];
__device__ __nv_bfloat16 g_Wl0[262144];
__device__ __nv_bfloat16 g_Wh1[262144];
__device__ __nv_bfloat16 g_Wl1[262144];
__device__ __nv_bfloat16 g_Wh2[262144];
__device__ __nv_bfloat16 g_Wl2[262144];

__device__ __forceinline__ uint32_t smem_to_u32(const void* p) {
    uint32_t a;
    asm("{ .reg .u64 t; cvta.to.shared.u64 t, %1; cvt.u32.u64 %0, t; }"
        : "=r"(a) : "l"(p));
    return a;
}

// ---------------------------------------------------------------------------
// split kernels
// ---------------------------------------------------------------------------
__device__ __forceinline__ void split_store4(
    __nv_bfloat16* h, __nv_bfloat16* l, long i, float4 v)
{
    __nv_bfloat16 h0 = __float2bfloat16(v.x);
    __nv_bfloat16 h1 = __float2bfloat16(v.y);
    __nv_bfloat16 h2 = __float2bfloat16(v.z);
    __nv_bfloat16 h3 = __float2bfloat16(v.w);
    __nv_bfloat16 l0 = __float2bfloat16(v.x - __bfloat162float(h0));
    __nv_bfloat16 l1 = __float2bfloat16(v.y - __bfloat162float(h1));
    __nv_bfloat16 l2 = __float2bfloat16(v.z - __bfloat162float(h2));
    __nv_bfloat16 l3 = __float2bfloat16(v.w - __bfloat162float(h3));
    __nv_bfloat162* hp = (__nv_bfloat162*)(h + i * 4);
    __nv_bfloat162* lp = (__nv_bfloat162*)(l + i * 4);
    hp[0] = __nv_bfloat162(h0, h1); hp[1] = __nv_bfloat162(h2, h3);
    lp[0] = __nv_bfloat162(l0, l1); lp[1] = __nv_bfloat162(l2, l3);
}

__global__ __launch_bounds__(256) void split_a2_kernel(
    const float* __restrict__ x0, const float* __restrict__ x1,
    __nv_bfloat16* __restrict__ h0, __nv_bfloat16* __restrict__ l0,
    __nv_bfloat16* __restrict__ h1, __nv_bfloat16* __restrict__ l1,
    long n4)
{
    long i = (long)blockIdx.x * 256 + threadIdx.x;
    if (i >= n4) return;
    const float* x = blockIdx.y ? x1 : x0;
    __nv_bfloat16* h = blockIdx.y ? h1 : h0;
    __nv_bfloat16* l = blockIdx.y ? l1 : l0;
    split_store4(h, l, i, *(const float4*)(x + i * 4));
}

__global__ __launch_bounds__(256) void split_wt3_kernel(
    const float* __restrict__ W0, const float* __restrict__ W1,
    const float* __restrict__ W2,
    __nv_bfloat16* __restrict__ h0, __nv_bfloat16* __restrict__ l0,
    __nv_bfloat16* __restrict__ h1, __nv_bfloat16* __restrict__ l1,
    __nv_bfloat16* __restrict__ h2, __nv_bfloat16* __restrict__ l2)
{
    __shared__ float t[32][33];
    int tx = threadIdx.x, ty = threadIdx.y;
    int bx = blockIdx.x, by = blockIdx.y, bz = blockIdx.z;
    const float* W = bz == 0 ? W0 : (bz == 1 ? W1 : W2);
    __nv_bfloat16* hT = bz == 0 ? h0 : (bz == 1 ? h1 : h2);
    __nv_bfloat16* lT = bz == 0 ? l0 : (bz == 1 ? l1 : l2);
#pragma unroll
    for (int j = 0; j < 4; j++)
        t[ty + 8 * j][tx] = W[(size_t)(by * 32 + ty + 8 * j) * 512 + bx * 32 + tx];
    __syncthreads();
#pragma unroll
    for (int j = 0; j < 4; j++) {
        float v = t[tx][ty + 8 * j];
        int n_o = bx * 32 + ty + 8 * j;
        int k_o = by * 32 + tx;
        __nv_bfloat16 hb = __float2bfloat16(v);
        __nv_bfloat16 lb = __float2bfloat16(v - __bfloat162float(hb));
        hT[(size_t)n_o * 512 + k_o] = hb;
        lT[(size_t)n_o * 512 + k_o] = lb;
    }
}

// ---------------------------------------------------------------------------
// bf16x3 GEMM core
// ---------------------------------------------------------------------------
#define LDAE 40
#define ARR_B (128 * LDAE * 2)
#define BUF_B (4 * ARR_B)
#define GSMEM_BYTES (2 * BUF_B)

#define CP_ASYNC16(dst, src) \
    asm volatile("cp.async.cg.shared.global [%0], [%1], 16;" \
        :: "r"(dst), "l"(src))
#define CP_COMMIT() asm volatile("cp.async.commit_group;" ::: "memory")
#define CP_WAIT1() asm volatile("cp.async.wait_group 1;" ::: "memory")
#define CP_WAIT0() asm volatile("cp.async.wait_group 0;" ::: "memory")

#define LDSM_X4(R, addr) \
    asm volatile("ldmatrix.sync.aligned.m8n8.x4.shared.b16 {%0,%1,%2,%3}, [%4];" \
        : "=r"((R)[0]), "=r"((R)[1]), "=r"((R)[2]), "=r"((R)[3]) : "r"(addr))
#define LDSM_X2(R, addr) \
    asm volatile("ldmatrix.sync.aligned.m8n8.x2.shared.b16 {%0,%1}, [%2];" \
        : "=r"((R)[0]), "=r"((R)[1]) : "r"(addr))

#define MMA_BF16(ACC, A, B0, B1) \
    asm volatile( \
        "mma.sync.aligned.m16n8k16.row.col.f32.bf16.bf16.f32 " \
        "{%0,%1,%2,%3}, {%4,%5,%6,%7}, {%8,%9}, {%0,%1,%2,%3};" \
        : "+f"((ACC)[0]), "+f"((ACC)[1]), "+f"((ACC)[2]), "+f"((ACC)[3]) \
        : "r"((A)[0]), "r"((A)[1]), "r"((A)[2]), "r"((A)[3]), \
          "r"(B0), "r"(B1))

__device__ __forceinline__ void gemm_core(
    char* dsm,
    const __nv_bfloat16* __restrict__ Ah, const __nv_bfloat16* __restrict__ Al,
    const __nv_bfloat16* __restrict__ Bh, const __nv_bfloat16* __restrict__ Bl,
    const float* __restrict__ bias, float* __restrict__ C)
{
    const int tid = threadIdx.x;
    const int wid = tid >> 5, lane = tid & 31;
    const int bm = blockIdx.y * 128, bn = blockIdx.x * 128;
    const int wm = (wid >> 2) * 64, wn = (wid & 3) * 32;
    const int lr = lane >> 2, lc = lane & 3;
    const uint32_t sb = smem_to_u32(dsm);

    float acc[4][4][4];
#pragma unroll
    for (int mi = 0; mi < 4; mi++)
#pragma unroll
        for (int ni = 0; ni < 4; ni++)
#pragma unroll
            for (int r = 0; r < 4; r++) acc[mi][ni][r] = 0.f;

    const __nv_bfloat16* gsrc0 = Ah + (size_t)bm * 512;
    const __nv_bfloat16* gsrc1 = Al + (size_t)bm * 512;
    const __nv_bfloat16* gsrc2 = Bh + (size_t)bn * 512;
    const __nv_bfloat16* gsrc3 = Bl + (size_t)bn * 512;

    const int pc0 = tid, pc1 = tid + 256;
    const int pr0 = pc0 >> 2, po0 = (pc0 & 3);
    const int pr1 = pc1 >> 2, po1 = (pc1 & 3);

#define PRODUCE(KB, BUF) do {                                                  \
    uint32_t base = sb + (BUF) * BUF_B;                                        \
    int kg = (KB) * 32;                                                        \
    CP_ASYNC16(base + pr0 * 80 + po0 * 16,                                     \
               gsrc0 + (size_t)pr0 * 512 + kg + po0 * 8);                      \
    CP_ASYNC16(base + pr1 * 80 + po1 * 16,                                     \
               gsrc0 + (size_t)pr1 * 512 + kg + po1 * 8);                      \
    CP_ASYNC16(base + ARR_B + pr0 * 80 + po0 * 16,                             \
               gsrc1 + (size_t)pr0 * 512 + kg + po0 * 8);                      \
    CP_ASYNC16(base + ARR_B + pr1 * 80 + po1 * 16,                             \
               gsrc1 + (size_t)pr1 * 512 + kg + po1 * 8);                      \
    CP_ASYNC16(base + 2 * ARR_B + pr0 * 80 + po0 * 16,                         \
               gsrc2 + (size_t)pr0 * 512 + kg + po0 * 8);                      \
    CP_ASYNC16(base + 2 * ARR_B + pr1 * 80 + po1 * 16,                         \
               gsrc2 + (size_t)pr1 * 512 + kg + po1 * 8);                      \
    CP_ASYNC16(base + 3 * ARR_B + pr0 * 80 + po0 * 16,                         \
               gsrc3 + (size_t)pr0 * 512 + kg + po0 * 8);                      \
    CP_ASYNC16(base + 3 * ARR_B + pr1 * 80 + po1 * 16,                         \
               gsrc3 + (size_t)pr1 * 512 + kg + po1 * 8);                      \
    CP_COMMIT();                                                               \
} while (0)

    const int a_row_off = (lane & 7) + ((lane >> 3) & 1) * 8;
    const int a_k_off = (lane >> 4) * 8;
    const int b_row_off = lane & 7;
    const int b_k_off = ((lane >> 3) & 1) * 8;

    PRODUCE(0, 0);
    for (int kb = 0; kb < 16; kb++) {
        if (kb < 15) PRODUCE(kb + 1, (kb + 1) & 1);
        if (kb < 15) { CP_WAIT1(); } else { CP_WAIT0(); }
        __syncthreads();
        const uint32_t base = sb + (kb & 1) * BUF_B;

#pragma unroll
        for (int k16 = 0; k16 < 32; k16 += 16) {
            uint32_t ah[4][4], al[4][4], bh[4][2], bl[4][2];
#pragma unroll
            for (int mi = 0; mi < 4; mi++) {
                uint32_t addr = base +
                    ((wm + mi * 16 + a_row_off) * LDAE + k16 + a_k_off) * 2;
                LDSM_X4(ah[mi], addr);
                LDSM_X4(al[mi], addr + ARR_B);
            }
#pragma unroll
            for (int ni = 0; ni < 4; ni++) {
                uint32_t addr = base + 2 * ARR_B +
                    ((wn + ni * 8 + b_row_off) * LDAE + k16 + b_k_off) * 2;
                LDSM_X2(bh[ni], addr);
                LDSM_X2(bl[ni], addr + ARR_B);
            }
#pragma unroll
            for (int mi = 0; mi < 4; mi++)
#pragma unroll
                for (int ni = 0; ni < 4; ni++) {
                    MMA_BF16(acc[mi][ni], ah[mi], bh[ni][0], bh[ni][1]);
                    MMA_BF16(acc[mi][ni], ah[mi], bl[ni][0], bl[ni][1]);
                    MMA_BF16(acc[mi][ni], al[mi], bh[ni][0], bh[ni][1]);
                }
        }
        __syncthreads();
    }

#pragma unroll
    for (int mi = 0; mi < 4; mi++) {
#pragma unroll
        for (int ni = 0; ni < 4; ni++) {
            int col = bn + wn + ni * 8 + 2 * lc;
            float2 bv = *(const float2*)(bias + col);
            int r0 = bm + wm + mi * 16 + lr;
            float2 o0 = make_float2(acc[mi][ni][0] + bv.x, acc[mi][ni][1] + bv.y);
            float2 o1 = make_float2(acc[mi][ni][2] + bv.x, acc[mi][ni][3] + bv.y);
            *(float2*)(C + (size_t)r0 * 512 + col) = o0;
            *(float2*)(C + (size_t)(r0 + 8) * 512 + col) = o1;
        }
    }
#undef PRODUCE
}

__global__ __launch_bounds__(256, 2) void gemm_bf16x3(
    const __nv_bfloat16* __restrict__ Ah, const __nv_bfloat16* __restrict__ Al,
    const __nv_bfloat16* __restrict__ Bh, const __nv_bfloat16* __restrict__ Bl,
    const float* __restrict__ bias, float* __restrict__ C)
{
    extern __shared__ __align__(16) char dsm[];
    gemm_core(dsm, Ah, Al, Bh, Bl, bias, C);
}

__global__ __launch_bounds__(256, 2) void gemm_bf16x3_dual(
    const __nv_bfloat16* __restrict__ Ah0, const __nv_bfloat16* __restrict__ Al0,
    const __nv_bfloat16* __restrict__ Bh0, const __nv_bfloat16* __restrict__ Bl0,
    const float* __restrict__ b0, float* __restrict__ C0,
    const __nv_bfloat16* __restrict__ Ah1, const __nv_bfloat16* __restrict__ Al1,
    const __nv_bfloat16* __restrict__ Bh1, const __nv_bfloat16* __restrict__ Bl1,
    const float* __restrict__ b1, float* __restrict__ C1)
{
    extern __shared__ __align__(16) char dsm[];
    if (blockIdx.z == 0)
        gemm_core(dsm, Ah0, Al0, Bh0, Bl0, b0, C0);
    else
        gemm_core(dsm, Ah1, Al1, Bh1, Bl1, b1, C1);
}

// ---------------------------------------------------------------------------
// Wavelet step — q and k in one launch
// ---------------------------------------------------------------------------
__global__ __launch_bounds__(256) void wavelet2_kernel(
    const float* __restrict__ xq, const float* __restrict__ xk,
    const float* __restrict__ ecd, const float* __restrict__ ecs,
    float* __restrict__ dq, float* __restrict__ qn,
    float* __restrict__ dk, float* __restrict__ kn, int Lh)
{
    __shared__ float wd[16][8], ws_[16][8];
    int tid = threadIdx.x;
    if (tid < 128)       wd[tid >> 3][tid & 7] = ecd[tid];
    else if (tid < 256)  { int t = tid - 128; ws_[t >> 3][t & 7] = ecs[t]; }
    __syncthreads();

    const float* x = blockIdx.y ? xk : xq;
    float* od = blockIdx.y ? dk : dq;
    float* os = blockIdx.y ? kn : qn;

    long idx = (long)blockIdx.x * 256 + tid;
    long total = (long)BB * Lh * 64;
    if (idx >= total) return;
    int c = (int)(idx & 63);
    long bt = idx >> 6;
    int t2 = (int)(bt % Lh);
    int b = (int)(bt / Lh);

    const float* p0 = x + ((long)(b * 2 * Lh + 2 * t2)) * CKD + c * 8;
    float a[16];
    *(float4*)(a)      = *(const float4*)(p0);
    *(float4*)(a + 4)  = *(const float4*)(p0 + 4);
    *(float4*)(a + 8)  = *(const float4*)(p0 + CKD);
    *(float4*)(a + 12) = *(const float4*)(p0 + CKD + 4);

    float rd[8], rs[8];
#pragma unroll
    for (int kk = 0; kk < 8; kk++) { rd[kk] = 0.f; rs[kk] = 0.f; }
#pragma unroll
    for (int j = 0; j < 16; j++)
#pragma unroll
        for (int kk = 0; kk < 8; kk++) {
            rd[kk] += a[j] * wd[j][kk];
            rs[kk] += a[j] * ws_[j][kk];
        }
    float* pd = od + ((long)(b * Lh + t2)) * CKD + c * 8;
    float* ps = os + ((long)(b * Lh + t2)) * CKD + c * 8;
    *(float4*)(pd)     = *(float4*)(rd);
    *(float4*)(pd + 4) = *(float4*)(rd + 4);
    *(float4*)(ps)     = *(float4*)(rs);
    *(float4*)(ps + 4) = *(float4*)(rs + 4);
}

// ---------------------------------------------------------------------------
// Reconstruction step (optionally emits bf16 hi/lo split)
// ---------------------------------------------------------------------------
__global__ __launch_bounds__(256) void recon_kernel(
    const float* __restrict__ vin, const float* __restrict__ us,
    const float* __restrict__ ud, const float* __restrict__ rce,
    const float* __restrict__ rco, float* __restrict__ vout, int Lv,
    __nv_bfloat16* __restrict__ oh, __nv_bfloat16* __restrict__ ol,
    int do_split)
{
    __shared__ float we[16][8], wo[16][8];
    int tid = threadIdx.x;
    if (tid < 128)       we[tid >> 3][tid & 7] = rce[tid];
    else if (tid < 256)  { int t = tid - 128; wo[t >> 3][t & 7] = rco[t]; }
    __syncthreads();

    long idx = (long)blockIdx.x * 256 + tid;
    long total = (long)BB * Lv * 64;
    if (idx >= total) return;
    int c = (int)(idx & 63);
    long bt = idx >> 6;
    int t = (int)(bt % Lv);
    int b = (int)(bt / Lv);

    long base = ((long)(b * Lv + t)) * CKD + c * 8;
    float a[16];
#pragma unroll
    for (int j = 0; j < 8; j++) a[j] = vin[base + j] + us[base + j];
    *(float4*)(a + 8)  = *(const float4*)(ud + base);
    *(float4*)(a + 12) = *(const float4*)(ud + base + 4);

    float re[8], ro[8];
#pragma unroll
    for (int kk = 0; kk < 8; kk++) { re[kk] = 0.f; ro[kk] = 0.f; }
#pragma unroll
    for (int j = 0; j < 16; j++)
#pragma unroll
        for (int kk = 0; kk < 8; kk++) {
            re[kk] += a[j] * we[j][kk];
            ro[kk] += a[j] * wo[j][kk];
        }
    long obase = ((long)(b * 2 * Lv + 2 * t)) * CKD + c * 8;
    float* pe = vout + obase;
    *(float4*)(pe)           = *(float4*)(re);
    *(float4*)(pe + 4)       = *(float4*)(re + 4);
    *(float4*)(pe + CKD)     = *(float4*)(ro);
    *(float4*)(pe + CKD + 4) = *(float4*)(ro + 4);

    if (do_split) {
        split_store4(oh, ol, (obase >> 2),           *(float4*)(re));
        split_store4(oh, ol, (obase >> 2) + 1,       *(float4*)(re + 4));
        split_store4(oh, ol, ((obase + CKD) >> 2),     *(float4*)(ro));
        split_store4(oh, ol, ((obase + CKD) >> 2) + 1, *(float4*)(ro + 4));
    }
}

// ---------------------------------------------------------------------------
// rfft x4 streams
// ---------------------------------------------------------------------------
__global__ __launch_bounds__(256) void rfft4_kernel(
    const float* __restrict__ s0, const float* __restrict__ s1,
    const float* __restrict__ s2, const float* __restrict__ s3,
    float2* __restrict__ F0, float2* __restrict__ F1,
    float2* __restrict__ F2, float2* __restrict__ F3,
    int L, int m)
{
    __shared__ float twc[512], tws[512];
    __shared__ float tile[64][64];
    int tid = threadIdx.x;
    int ec = blockIdx.x;
    int b = blockIdx.y;
    int z = blockIdx.z;
    const float* x = z == 0 ? s0 : (z == 1 ? s1 : (z == 2 ? s2 : s3));
    float2* F = z == 0 ? F0 : (z == 1 ? F1 : (z == 2 ? F2 : F3));

    for (int i = tid; i < L; i += 256) {
        float th = 6.2831853071795864f * (float)i / (float)L;
        float s, c; sincosf(th, &s, &c);
        twc[i] = c; tws[i] = s;
    }

    int eh = tid >> 2;
    int xg = tid & 3;
    float ar[4] = {0.f, 0.f, 0.f, 0.f}, ai[4] = {0.f, 0.f, 0.f, 0.f};

    for (int t0 = 0; t0 < L; t0 += 64) {
        int tc = L - t0 < 64 ? L - t0 : 64;
        __syncthreads();
        for (int i = tid; i < tc * 64; i += 256) {
            int tt = i >> 6, el = i & 63;
            tile[tt][el] = x[((long)(b * L + t0 + tt)) * CKD + ec * 64 + el];
        }
        __syncthreads();
        for (int tt = 0; tt < tc; tt++) {
            float v = tile[tt][eh];
            int t = t0 + tt;
#pragma unroll
            for (int j = 0; j < 4; j++) {
                int xx = xg + j * 4;
                int id = (xx * t) & (L - 1);
                ar[j] += v * twc[id];
                ai[j] -= v * tws[id];
            }
        }
    }
    int e = ec * 8 + (eh >> 3), h = eh & 7;
    float2* dst = F + ((long)((b * 8 + h) * 64 + e)) * 16;
#pragma unroll
    for (int j = 0; j < 4; j++) {
        int xx = xg + j * 4;
        if (xx < m) dst[xx] = make_float2(ar[j], ai[j]);
    }
}

// ---------------------------------------------------------------------------
// attn x2 pairs
// ---------------------------------------------------------------------------
__global__ __launch_bounds__(256) void attn2_kernel(
    const float2* __restrict__ QFs, const float2* __restrict__ KFs,
    float2* __restrict__ OFs,
    const float2* __restrict__ QFd, const float2* __restrict__ KFd,
    float2* __restrict__ OFd, int m)
{
    __shared__ float2 qf[1024], kf[1024], S[256];
    int bh = blockIdx.x & 127, pair = blockIdx.x >> 7;
    int tid = threadIdx.x;
    const float2* QF = pair ? QFd : QFs;
    const float2* KF = pair ? KFd : KFs;
    float2* OF = pair ? OFd : OFs;
    const float2* qsrc = QF + (long)bh * 1024;
    const float2* ksrc = KF + (long)bh * 1024;
    for (int i = tid; i < 1024; i += 256) { qf[i] = qsrc[i]; kf[i] = ksrc[i]; }
    __syncthreads();

    for (int s = tid; s < m * m; s += 256) {
        int xx = s / m, yy = s - xx * m;
        float re = 0.f, im = 0.f;
#pragma unroll 8
        for (int e = 0; e < 64; e++) {
            float2 qv = qf[e * 16 + xx], kv = kf[e * 16 + yy];
            re += qv.x * kv.x - qv.y * kv.y;
            im += qv.x * kv.y + qv.y * kv.x;
        }
        float X = 2.f * re, Y = 2.f * im, orr, oii;
        if (fabsf(X) > 20.f) {
            orr = copysignf(1.f, X); oii = 0.f;
        } else {
            float ex = expf(X), enx = 1.f / ex;
            float sh = 0.5f * (ex - enx), ch = 0.5f * (ex + enx);
            float sy, cy; sincosf(Y, &sy, &cy);
            float den = ch + cy;
            orr = sh / den; oii = sy / den;
        }
        S[xx * 16 + yy] = make_float2(orr, oii);
    }
    __syncthreads();
    for (int o = tid; o < 64 * m; o += 256) {
        int e = o / m, xx = o - e * m;
        float re = 0.f, im = 0.f;
        for (int yy = 0; yy < m; yy++) {
            float2 sv = S[xx * 16 + yy], kv = kf[e * 16 + yy];
            re += sv.x * kv.x - sv.y * kv.y;
            im += sv.x * kv.y + sv.y * kv.x;
        }
        OF[(long)bh * 1024 + e * 16 + xx] = make_float2(re, im);
    }
}

// ---------------------------------------------------------------------------
// irfft x2
// ---------------------------------------------------------------------------
__global__ __launch_bounds__(256) void irfft2_kernel(
    const float2* __restrict__ OFs, const float2* __restrict__ OFd,
    float* __restrict__ US, float* __restrict__ UD, int L, int m)
{
    __shared__ float twc[512], tws[512];
    __shared__ float2 of_s[64][16];
    int tid = threadIdx.x, ec = blockIdx.x, b = blockIdx.y, z = blockIdx.z;
    float* out = z ? UD : US;

    for (int i = tid; i < L; i += 256) {
        float th = 6.2831853071795864f * (float)i / (float)L;
        float s, c; sincosf(th, &s, &c);
        twc[i] = c; tws[i] = s;
    }
    float inv = 1.f / ((float)L * 4096.f);
    for (int i = tid; i < 1024; i += 256) {
        int el = i >> 4, xx = i & 15;
        int e = ec * 8 + (el >> 3), h = el & 7;
        float2 v = make_float2(0.f, 0.f);
        if (xx < m) {
            long src = ((long)((b * 8 + h) * 64 + e)) * 16 + xx;
            v = OFs[src];
            if (z) { float2 d = OFd[src]; v.x += d.x; v.y += d.y; }
        }
        float w = (xx == 0) ? inv : 2.f * inv;
        of_s[el][xx] = make_float2(v.x * w, v.y * w);
    }
    __syncthreads();

    for (long i = tid; i < (long)L * 64; i += 256) {
        int el = (int)(i & 63);
        int t = (int)(i >> 6);
        float acc = 0.f;
#pragma unroll
        for (int xx = 0; xx < 16; xx++) {
            int id = (xx * t) & (L - 1);
            float2 f = of_s[el][xx];
            acc += f.x * twc[id] - f.y * tws[id];
        }
        long dst = ((long)(b * L + t)) * CKD + ec * 64 + el;
        out[dst] = acc;
    }
}

__global__ void zero2_kernel(float* p0, float* p1, long n) {
    long i = (long)blockIdx.x * blockDim.x + threadIdx.x;
    if (i < n) { p0[i] = 0.f; p1[i] = 0.f; }
}

// ---------------------------------------------------------------------------
extern "C" void kernel_launch(void* const* d_in, const int* in_sizes, int n_in,
                              void* d_out, int out_size)
{
    const float* q    = (const float*)d_in[0];
    const float* k    = (const float*)d_in[1];
    const float* Lq_w = (const float*)d_in[3];
    const float* Lq_b = (const float*)d_in[4];
    const float* Lk_w = (const float*)d_in[5];
    const float* Lk_b = (const float*)d_in[6];
    const float* out_w = (const float*)d_in[9];
    const float* out_b = (const float*)d_in[10];
    const float* ec_s = (const float*)d_in[11];
    const float* ec_d = (const float*)d_in[12];
    const float* rc_e = (const float*)d_in[13];
    const float* rc_o = (const float*)d_in[14];

    float *QA, *QB, *KA, *KB, *DQ, *DK, *US, *UD, *VA, *VB;
    float2 *QFs, *KFs, *QFd, *KFd, *OFs, *OFd;
    __nv_bfloat16 *Ah, *Al, *Ah2, *Al2, *Wh0, *Wl0, *Wh1, *Wl1, *Wh2, *Wl2;
    cudaGetSymbolAddress((void**)&QA, g_QA);
    cudaGetSymbolAddress((void**)&QB, g_QB);
    cudaGetSymbolAddress((void**)&KA, g_KA);
    cudaGetSymbolAddress((void**)&KB, g_KB);
    cudaGetSymbolAddress((void**)&DQ, g_DQ);
    cudaGetSymbolAddress((void**)&DK, g_DK);
    cudaGetSymbolAddress((void**)&US, g_US);
    cudaGetSymbolAddress((void**)&UD, g_UD);
    cudaGetSymbolAddress((void**)&VA, g_VA);
    cudaGetSymbolAddress((void**)&VB, g_VB);
    cudaGetSymbolAddress((void**)&QFs, g_QFs);
    cudaGetSymbolAddress((void**)&KFs, g_KFs);
    cudaGetSymbolAddress((void**)&QFd, g_QFd);
    cudaGetSymbolAddress((void**)&KFd, g_KFd);
    cudaGetSymbolAddress((void**)&OFs, g_OFs);
    cudaGetSymbolAddress((void**)&OFd, g_OFd);
    cudaGetSymbolAddress((void**)&Ah, g_Ah);
    cudaGetSymbolAddress((void**)&Al, g_Al);
    cudaGetSymbolAddress((void**)&Ah2, g_Ah2);
    cudaGetSymbolAddress((void**)&Al2, g_Al2);
    cudaGetSymbolAddress((void**)&Wh0, g_Wh0);
    cudaGetSymbolAddress((void**)&Wl0, g_Wl0);
    cudaGetSymbolAddress((void**)&Wh1, g_Wh1);
    cudaGetSymbolAddress((void**)&Wl1, g_Wl1);
    cudaGetSymbolAddress((void**)&Wh2, g_Wh2);
    cudaGetSymbolAddress((void**)&Wl2, g_Wl2);

    cudaFuncSetAttribute(gemm_bf16x3,
                         cudaFuncAttributeMaxDynamicSharedMemorySize,
                         GSMEM_BYTES);
    cudaFuncSetAttribute(gemm_bf16x3_dual,
                         cudaFuncAttributeMaxDynamicSharedMemorySize,
                         GSMEM_BYTES);

    // weight splits (all three) + input splits (q,k) + dual projection GEMM
    split_wt3_kernel<<<dim3(16, 16, 3), dim3(32, 8)>>>(
        Lq_w, Lk_w, out_w, Wh0, Wl0, Wh1, Wl1, Wh2, Wl2);
    split_a2_kernel<<<dim3(8192, 2), 256>>>(q, k, Ah, Al, Ah2, Al2, 2097152);
    gemm_bf16x3_dual<<<dim3(4, 128, 2), 256, GSMEM_BYTES>>>(
        Ah, Al, Wh0, Wl0, Lq_b, QA,
        Ah2, Al2, Wh1, Wl1, Lk_b, KA);

    float* qc = QA; float* qn = QB;
    float* kc = KA; float* kn = KB;
    long offs[10]; int Lhs[10];
    long off = 0;
    int L = 1024;
    for (int i = 0; i < 10; i++) {
        int Lh = L >> 1;
        Lhs[i] = Lh; offs[i] = off;
        off += (long)BB * Lh * CKD;
        int m = (Lh / 2 < 16) ? (Lh / 2) : 16;
        long total = (long)BB * Lh * 64;
        int blocks = (int)((total + 255) / 256);

        wavelet2_kernel<<<dim3(blocks, 2), 256>>>(
            qc, kc, ec_d, ec_s, DQ, qn, DK, kn, Lh);

        long sz = (long)BB * Lh * CKD;
        if (m > 0) {
            rfft4_kernel<<<dim3(8, BB, 4), 256>>>(
                DQ, DK, qn, kn, QFs, KFs, QFd, KFd, Lh, m);
            attn2_kernel<<<256, 256>>>(QFs, KFs, OFs, QFd, KFd, OFd, m);
            irfft2_kernel<<<dim3(8, BB, 2), 256>>>(
                OFs, OFd, US + offs[i], UD + offs[i], Lh, m);
        } else {
            zero2_kernel<<<(int)((sz + 255) / 256), 256>>>(
                US + offs[i], UD + offs[i], sz);
        }
        { float* t = qc; qc = qn; qn = t; }
        { float* t = kc; kc = kn; kn = t; }
        L = Lh;
    }

    zero2_kernel<<<32, 256>>>(VA, VA, (long)BB * 1 * CKD);
    float* vc = VA; float* vn = VB;
    for (int i = 9; i >= 0; i--) {
        int Lv = Lhs[i];
        long total = (long)BB * Lv * 64;
        recon_kernel<<<(int)((total + 255) / 256), 256>>>(
            vc, US + offs[i], UD + offs[i], rc_e, rc_o, vn, Lv,
            Ah, Al, (i == 0) ? 1 : 0);
        float* t = vc; vc = vn; vn = t;
    }

    // Output projection (recon already emitted the bf16 split into Ah/Al)
    gemm_bf16x3<<<dim3(4, 128), 256, GSMEM_BYTES>>>(
        Ah, Al, Wh2, Wl2, out_b, (float*)d_out);
}

// round 13
// speedup vs baseline: 2.0079x; 1.0180x over previous
#include <cuda_runtime.h>
#include <cuda_bf16.h>
#include <math.h>
#include <cstdint>

// ---------------------------------------------------------------------------
// MultiWaveletCross on GB300 — round 13: round-12 (840us) + DFT LDS-ratio
// fixes: float2 twiddles (rfft/irfft) + of_s register hoist (irfft)
// ---------------------------------------------------------------------------

#define BB 16
#define CKD 512
#define NTOK 16384

__device__ float g_QA[8388608];
__device__ float g_QB[8388608];
__device__ float g_KA[8388608];
__device__ float g_KB[8388608];
__device__ float g_DQ[4194304];
__device__ float g_DK[4194304];
__device__ float g_US[8380416];
__device__ float g_UD[8380416];
__device__ float g_VA[8388608];
__device__ float g_VB[8388608];
__device__ float2 g_QFs[131072];
__device__ float2 g_KFs[131072];
__device__ float2 g_QFd[131072];
__device__ float2 g_KFd[131072];
__device__ float2 g_OFs[131072];
__device__ float2 g_OFd[131072];
// bf16 split scratch
__device__ __nv_bfloat16 g_Ah[8388608];
__device__ __nv_bfloat16 g_Al[8388608];
__device__ __nv_bfloat16 g_Ah2[8388608];
__device__ __nv_bfloat16 g_Al2[8388608];
__device__ __nv_bfloat16 g_Wh0[262144];
__device__ __nv_bfloat16 g_Wl0[262144];
__device__ __nv_bfloat16 g_Wh1[262144];
__device__ __nv_bfloat16 g_Wl1[262144];
__device__ __nv_bfloat16 g_Wh2[262144];
__device__ __nv_bfloat16 g_Wl2[262144];

__device__ __forceinline__ uint32_t smem_to_u32(const void* p) {
    uint32_t a;
    asm("{ .reg .u64 t; cvta.to.shared.u64 t, %1; cvt.u32.u64 %0, t; }"
        : "=r"(a) : "l"(p));
    return a;
}

// ---------------------------------------------------------------------------
// split kernels
// ---------------------------------------------------------------------------
__device__ __forceinline__ void split_store4(
    __nv_bfloat16* h, __nv_bfloat16* l, long i, float4 v)
{
    __nv_bfloat16 h0 = __float2bfloat16(v.x);
    __nv_bfloat16 h1 = __float2bfloat16(v.y);
    __nv_bfloat16 h2 = __float2bfloat16(v.z);
    __nv_bfloat16 h3 = __float2bfloat16(v.w);
    __nv_bfloat16 l0 = __float2bfloat16(v.x - __bfloat162float(h0));
    __nv_bfloat16 l1 = __float2bfloat16(v.y - __bfloat162float(h1));
    __nv_bfloat16 l2 = __float2bfloat16(v.z - __bfloat162float(h2));
    __nv_bfloat16 l3 = __float2bfloat16(v.w - __bfloat162float(h3));
    __nv_bfloat162* hp = (__nv_bfloat162*)(h + i * 4);
    __nv_bfloat162* lp = (__nv_bfloat162*)(l + i * 4);
    hp[0] = __nv_bfloat162(h0, h1); hp[1] = __nv_bfloat162(h2, h3);
    lp[0] = __nv_bfloat162(l0, l1); lp[1] = __nv_bfloat162(l2, l3);
}

__global__ __launch_bounds__(256) void split_a2_kernel(
    const float* __restrict__ x0, const float* __restrict__ x1,
    __nv_bfloat16* __restrict__ h0, __nv_bfloat16* __restrict__ l0,
    __nv_bfloat16* __restrict__ h1, __nv_bfloat16* __restrict__ l1,
    long n4)
{
    long i = (long)blockIdx.x * 256 + threadIdx.x;
    if (i >= n4) return;
    const float* x = blockIdx.y ? x1 : x0;
    __nv_bfloat16* h = blockIdx.y ? h1 : h0;
    __nv_bfloat16* l = blockIdx.y ? l1 : l0;
    split_store4(h, l, i, *(const float4*)(x + i * 4));
}

__global__ __launch_bounds__(256) void split_wt3_kernel(
    const float* __restrict__ W0, const float* __restrict__ W1,
    const float* __restrict__ W2,
    __nv_bfloat16* __restrict__ h0, __nv_bfloat16* __restrict__ l0,
    __nv_bfloat16* __restrict__ h1, __nv_bfloat16* __restrict__ l1,
    __nv_bfloat16* __restrict__ h2, __nv_bfloat16* __restrict__ l2)
{
    __shared__ float t[32][33];
    int tx = threadIdx.x, ty = threadIdx.y;
    int bx = blockIdx.x, by = blockIdx.y, bz = blockIdx.z;
    const float* W = bz == 0 ? W0 : (bz == 1 ? W1 : W2);
    __nv_bfloat16* hT = bz == 0 ? h0 : (bz == 1 ? h1 : h2);
    __nv_bfloat16* lT = bz == 0 ? l0 : (bz == 1 ? l1 : l2);
#pragma unroll
    for (int j = 0; j < 4; j++)
        t[ty + 8 * j][tx] = W[(size_t)(by * 32 + ty + 8 * j) * 512 + bx * 32 + tx];
    __syncthreads();
#pragma unroll
    for (int j = 0; j < 4; j++) {
        float v = t[tx][ty + 8 * j];
        int n_o = bx * 32 + ty + 8 * j;
        int k_o = by * 32 + tx;
        __nv_bfloat16 hb = __float2bfloat16(v);
        __nv_bfloat16 lb = __float2bfloat16(v - __bfloat162float(hb));
        hT[(size_t)n_o * 512 + k_o] = hb;
        lT[(size_t)n_o * 512 + k_o] = lb;
    }
}

// ---------------------------------------------------------------------------
// bf16x3 GEMM core
// ---------------------------------------------------------------------------
#define LDAE 40
#define ARR_B (128 * LDAE * 2)
#define BUF_B (4 * ARR_B)
#define GSMEM_BYTES (2 * BUF_B)

#define CP_ASYNC16(dst, src) \
    asm volatile("cp.async.cg.shared.global [%0], [%1], 16;" \
        :: "r"(dst), "l"(src))
#define CP_COMMIT() asm volatile("cp.async.commit_group;" ::: "memory")
#define CP_WAIT1() asm volatile("cp.async.wait_group 1;" ::: "memory")
#define CP_WAIT0() asm volatile("cp.async.wait_group 0;" ::: "memory")

#define LDSM_X4(R, addr) \
    asm volatile("ldmatrix.sync.aligned.m8n8.x4.shared.b16 {%0,%1,%2,%3}, [%4];" \
        : "=r"((R)[0]), "=r"((R)[1]), "=r"((R)[2]), "=r"((R)[3]) : "r"(addr))
#define LDSM_X2(R, addr) \
    asm volatile("ldmatrix.sync.aligned.m8n8.x2.shared.b16 {%0,%1}, [%2];" \
        : "=r"((R)[0]), "=r"((R)[1]) : "r"(addr))

#define MMA_BF16(ACC, A, B0, B1) \
    asm volatile( \
        "mma.sync.aligned.m16n8k16.row.col.f32.bf16.bf16.f32 " \
        "{%0,%1,%2,%3}, {%4,%5,%6,%7}, {%8,%9}, {%0,%1,%2,%3};" \
        : "+f"((ACC)[0]), "+f"((ACC)[1]), "+f"((ACC)[2]), "+f"((ACC)[3]) \
        : "r"((A)[0]), "r"((A)[1]), "r"((A)[2]), "r"((A)[3]), \
          "r"(B0), "r"(B1))

__device__ __forceinline__ void gemm_core(
    char* dsm,
    const __nv_bfloat16* __restrict__ Ah, const __nv_bfloat16* __restrict__ Al,
    const __nv_bfloat16* __restrict__ Bh, const __nv_bfloat16* __restrict__ Bl,
    const float* __restrict__ bias, float* __restrict__ C)
{
    const int tid = threadIdx.x;
    const int wid = tid >> 5, lane = tid & 31;
    const int bm = blockIdx.y * 128, bn = blockIdx.x * 128;
    const int wm = (wid >> 2) * 64, wn = (wid & 3) * 32;
    const int lr = lane >> 2, lc = lane & 3;
    const uint32_t sb = smem_to_u32(dsm);

    float acc[4][4][4];
#pragma unroll
    for (int mi = 0; mi < 4; mi++)
#pragma unroll
        for (int ni = 0; ni < 4; ni++)
#pragma unroll
            for (int r = 0; r < 4; r++) acc[mi][ni][r] = 0.f;

    const __nv_bfloat16* gsrc0 = Ah + (size_t)bm * 512;
    const __nv_bfloat16* gsrc1 = Al + (size_t)bm * 512;
    const __nv_bfloat16* gsrc2 = Bh + (size_t)bn * 512;
    const __nv_bfloat16* gsrc3 = Bl + (size_t)bn * 512;

    const int pc0 = tid, pc1 = tid + 256;
    const int pr0 = pc0 >> 2, po0 = (pc0 & 3);
    const int pr1 = pc1 >> 2, po1 = (pc1 & 3);

#define PRODUCE(KB, BUF) do {                                                  \
    uint32_t base = sb + (BUF) * BUF_B;                                        \
    int kg = (KB) * 32;                                                        \
    CP_ASYNC16(base + pr0 * 80 + po0 * 16,                                     \
               gsrc0 + (size_t)pr0 * 512 + kg + po0 * 8);                      \
    CP_ASYNC16(base + pr1 * 80 + po1 * 16,                                     \
               gsrc0 + (size_t)pr1 * 512 + kg + po1 * 8);                      \
    CP_ASYNC16(base + ARR_B + pr0 * 80 + po0 * 16,                             \
               gsrc1 + (size_t)pr0 * 512 + kg + po0 * 8);                      \
    CP_ASYNC16(base + ARR_B + pr1 * 80 + po1 * 16,                             \
               gsrc1 + (size_t)pr1 * 512 + kg + po1 * 8);                      \
    CP_ASYNC16(base + 2 * ARR_B + pr0 * 80 + po0 * 16,                         \
               gsrc2 + (size_t)pr0 * 512 + kg + po0 * 8);                      \
    CP_ASYNC16(base + 2 * ARR_B + pr1 * 80 + po1 * 16,                         \
               gsrc2 + (size_t)pr1 * 512 + kg + po1 * 8);                      \
    CP_ASYNC16(base + 3 * ARR_B + pr0 * 80 + po0 * 16,                         \
               gsrc3 + (size_t)pr0 * 512 + kg + po0 * 8);                      \
    CP_ASYNC16(base + 3 * ARR_B + pr1 * 80 + po1 * 16,                         \
               gsrc3 + (size_t)pr1 * 512 + kg + po1 * 8);                      \
    CP_COMMIT();                                                               \
} while (0)

    const int a_row_off = (lane & 7) + ((lane >> 3) & 1) * 8;
    const int a_k_off = (lane >> 4) * 8;
    const int b_row_off = lane & 7;
    const int b_k_off = ((lane >> 3) & 1) * 8;

    PRODUCE(0, 0);
    for (int kb = 0; kb < 16; kb++) {
        if (kb < 15) PRODUCE(kb + 1, (kb + 1) & 1);
        if (kb < 15) { CP_WAIT1(); } else { CP_WAIT0(); }
        __syncthreads();
        const uint32_t base = sb + (kb & 1) * BUF_B;

#pragma unroll
        for (int k16 = 0; k16 < 32; k16 += 16) {
            uint32_t ah[4][4], al[4][4], bh[4][2], bl[4][2];
#pragma unroll
            for (int mi = 0; mi < 4; mi++) {
                uint32_t addr = base +
                    ((wm + mi * 16 + a_row_off) * LDAE + k16 + a_k_off) * 2;
                LDSM_X4(ah[mi], addr);
                LDSM_X4(al[mi], addr + ARR_B);
            }
#pragma unroll
            for (int ni = 0; ni < 4; ni++) {
                uint32_t addr = base + 2 * ARR_B +
                    ((wn + ni * 8 + b_row_off) * LDAE + k16 + b_k_off) * 2;
                LDSM_X2(bh[ni], addr);
                LDSM_X2(bl[ni], addr + ARR_B);
            }
#pragma unroll
            for (int mi = 0; mi < 4; mi++)
#pragma unroll
                for (int ni = 0; ni < 4; ni++) {
                    MMA_BF16(acc[mi][ni], ah[mi], bh[ni][0], bh[ni][1]);
                    MMA_BF16(acc[mi][ni], ah[mi], bl[ni][0], bl[ni][1]);
                    MMA_BF16(acc[mi][ni], al[mi], bh[ni][0], bh[ni][1]);
                }
        }
        __syncthreads();
    }

#pragma unroll
    for (int mi = 0; mi < 4; mi++) {
#pragma unroll
        for (int ni = 0; ni < 4; ni++) {
            int col = bn + wn + ni * 8 + 2 * lc;
            float2 bv = *(const float2*)(bias + col);
            int r0 = bm + wm + mi * 16 + lr;
            float2 o0 = make_float2(acc[mi][ni][0] + bv.x, acc[mi][ni][1] + bv.y);
            float2 o1 = make_float2(acc[mi][ni][2] + bv.x, acc[mi][ni][3] + bv.y);
            *(float2*)(C + (size_t)r0 * 512 + col) = o0;
            *(float2*)(C + (size_t)(r0 + 8) * 512 + col) = o1;
        }
    }
#undef PRODUCE
}

__global__ __launch_bounds__(256, 2) void gemm_bf16x3(
    const __nv_bfloat16* __restrict__ Ah, const __nv_bfloat16* __restrict__ Al,
    const __nv_bfloat16* __restrict__ Bh, const __nv_bfloat16* __restrict__ Bl,
    const float* __restrict__ bias, float* __restrict__ C)
{
    extern __shared__ __align__(16) char dsm[];
    gemm_core(dsm, Ah, Al, Bh, Bl, bias, C);
}

__global__ __launch_bounds__(256, 2) void gemm_bf16x3_dual(
    const __nv_bfloat16* __restrict__ Ah0, const __nv_bfloat16* __restrict__ Al0,
    const __nv_bfloat16* __restrict__ Bh0, const __nv_bfloat16* __restrict__ Bl0,
    const float* __restrict__ b0, float* __restrict__ C0,
    const __nv_bfloat16* __restrict__ Ah1, const __nv_bfloat16* __restrict__ Al1,
    const __nv_bfloat16* __restrict__ Bh1, const __nv_bfloat16* __restrict__ Bl1,
    const float* __restrict__ b1, float* __restrict__ C1)
{
    extern __shared__ __align__(16) char dsm[];
    if (blockIdx.z == 0)
        gemm_core(dsm, Ah0, Al0, Bh0, Bl0, b0, C0);
    else
        gemm_core(dsm, Ah1, Al1, Bh1, Bl1, b1, C1);
}

// ---------------------------------------------------------------------------
// Wavelet step — q and k in one launch
// ---------------------------------------------------------------------------
__global__ __launch_bounds__(256) void wavelet2_kernel(
    const float* __restrict__ xq, const float* __restrict__ xk,
    const float* __restrict__ ecd, const float* __restrict__ ecs,
    float* __restrict__ dq, float* __restrict__ qn,
    float* __restrict__ dk, float* __restrict__ kn, int Lh)
{
    __shared__ float wd[16][8], ws_[16][8];
    int tid = threadIdx.x;
    if (tid < 128)       wd[tid >> 3][tid & 7] = ecd[tid];
    else if (tid < 256)  { int t = tid - 128; ws_[t >> 3][t & 7] = ecs[t]; }
    __syncthreads();

    const float* x = blockIdx.y ? xk : xq;
    float* od = blockIdx.y ? dk : dq;
    float* os = blockIdx.y ? kn : qn;

    long idx = (long)blockIdx.x * 256 + tid;
    long total = (long)BB * Lh * 64;
    if (idx >= total) return;
    int c = (int)(idx & 63);
    long bt = idx >> 6;
    int t2 = (int)(bt % Lh);
    int b = (int)(bt / Lh);

    const float* p0 = x + ((long)(b * 2 * Lh + 2 * t2)) * CKD + c * 8;
    float a[16];
    *(float4*)(a)      = *(const float4*)(p0);
    *(float4*)(a + 4)  = *(const float4*)(p0 + 4);
    *(float4*)(a + 8)  = *(const float4*)(p0 + CKD);
    *(float4*)(a + 12) = *(const float4*)(p0 + CKD + 4);

    float rd[8], rs[8];
#pragma unroll
    for (int kk = 0; kk < 8; kk++) { rd[kk] = 0.f; rs[kk] = 0.f; }
#pragma unroll
    for (int j = 0; j < 16; j++)
#pragma unroll
        for (int kk = 0; kk < 8; kk++) {
            rd[kk] += a[j] * wd[j][kk];
            rs[kk] += a[j] * ws_[j][kk];
        }
    float* pd = od + ((long)(b * Lh + t2)) * CKD + c * 8;
    float* ps = os + ((long)(b * Lh + t2)) * CKD + c * 8;
    *(float4*)(pd)     = *(float4*)(rd);
    *(float4*)(pd + 4) = *(float4*)(rd + 4);
    *(float4*)(ps)     = *(float4*)(rs);
    *(float4*)(ps + 4) = *(float4*)(rs + 4);
}

// ---------------------------------------------------------------------------
// Reconstruction step (optionally emits bf16 hi/lo split)
// ---------------------------------------------------------------------------
__global__ __launch_bounds__(256) void recon_kernel(
    const float* __restrict__ vin, const float* __restrict__ us,
    const float* __restrict__ ud, const float* __restrict__ rce,
    const float* __restrict__ rco, float* __restrict__ vout, int Lv,
    __nv_bfloat16* __restrict__ oh, __nv_bfloat16* __restrict__ ol,
    int do_split)
{
    __shared__ float we[16][8], wo[16][8];
    int tid = threadIdx.x;
    if (tid < 128)       we[tid >> 3][tid & 7] = rce[tid];
    else if (tid < 256)  { int t = tid - 128; wo[t >> 3][t & 7] = rco[t]; }
    __syncthreads();

    long idx = (long)blockIdx.x * 256 + tid;
    long total = (long)BB * Lv * 64;
    if (idx >= total) return;
    int c = (int)(idx & 63);
    long bt = idx >> 6;
    int t = (int)(bt % Lv);
    int b = (int)(bt / Lv);

    long base = ((long)(b * Lv + t)) * CKD + c * 8;
    float a[16];
#pragma unroll
    for (int j = 0; j < 8; j++) a[j] = vin[base + j] + us[base + j];
    *(float4*)(a + 8)  = *(const float4*)(ud + base);
    *(float4*)(a + 12) = *(const float4*)(ud + base + 4);

    float re[8], ro[8];
#pragma unroll
    for (int kk = 0; kk < 8; kk++) { re[kk] = 0.f; ro[kk] = 0.f; }
#pragma unroll
    for (int j = 0; j < 16; j++)
#pragma unroll
        for (int kk = 0; kk < 8; kk++) {
            re[kk] += a[j] * we[j][kk];
            ro[kk] += a[j] * wo[j][kk];
        }
    long obase = ((long)(b * 2 * Lv + 2 * t)) * CKD + c * 8;
    float* pe = vout + obase;
    *(float4*)(pe)           = *(float4*)(re);
    *(float4*)(pe + 4)       = *(float4*)(re + 4);
    *(float4*)(pe + CKD)     = *(float4*)(ro);
    *(float4*)(pe + CKD + 4) = *(float4*)(ro + 4);

    if (do_split) {
        split_store4(oh, ol, (obase >> 2),           *(float4*)(re));
        split_store4(oh, ol, (obase >> 2) + 1,       *(float4*)(re + 4));
        split_store4(oh, ol, ((obase + CKD) >> 2),     *(float4*)(ro));
        split_store4(oh, ol, ((obase + CKD) >> 2) + 1, *(float4*)(ro + 4));
    }
}

// ---------------------------------------------------------------------------
// rfft x4 streams — float2 twiddles (1 LDS.64 per mode-tap)
// ---------------------------------------------------------------------------
__global__ __launch_bounds__(256) void rfft4_kernel(
    const float* __restrict__ s0, const float* __restrict__ s1,
    const float* __restrict__ s2, const float* __restrict__ s3,
    float2* __restrict__ F0, float2* __restrict__ F1,
    float2* __restrict__ F2, float2* __restrict__ F3,
    int L, int m)
{
    __shared__ float2 tw[512];
    __shared__ float tile[64][64];
    int tid = threadIdx.x;
    int ec = blockIdx.x;
    int b = blockIdx.y;
    int z = blockIdx.z;
    const float* x = z == 0 ? s0 : (z == 1 ? s1 : (z == 2 ? s2 : s3));
    float2* F = z == 0 ? F0 : (z == 1 ? F1 : (z == 2 ? F2 : F3));

    for (int i = tid; i < L; i += 256) {
        float th = 6.2831853071795864f * (float)i / (float)L;
        float s, c; sincosf(th, &s, &c);
        tw[i] = make_float2(c, s);
    }

    int eh = tid >> 2;
    int xg = tid & 3;
    float ar[4] = {0.f, 0.f, 0.f, 0.f}, ai[4] = {0.f, 0.f, 0.f, 0.f};

    for (int t0 = 0; t0 < L; t0 += 64) {
        int tc = L - t0 < 64 ? L - t0 : 64;
        __syncthreads();
        for (int i = tid; i < tc * 64; i += 256) {
            int tt = i >> 6, el = i & 63;
            tile[tt][el] = x[((long)(b * L + t0 + tt)) * CKD + ec * 64 + el];
        }
        __syncthreads();
        for (int tt = 0; tt < tc; tt++) {
            float v = tile[tt][eh];
            int t = t0 + tt;
#pragma unroll
            for (int j = 0; j < 4; j++) {
                int xx = xg + j * 4;
                int id = (xx * t) & (L - 1);
                float2 w = tw[id];
                ar[j] += v * w.x;
                ai[j] -= v * w.y;
            }
        }
    }
    int e = ec * 8 + (eh >> 3), h = eh & 7;
    float2* dst = F + ((long)((b * 8 + h) * 64 + e)) * 16;
#pragma unroll
    for (int j = 0; j < 4; j++) {
        int xx = xg + j * 4;
        if (xx < m) dst[xx] = make_float2(ar[j], ai[j]);
    }
}

// ---------------------------------------------------------------------------
// attn x2 pairs
// ---------------------------------------------------------------------------
__global__ __launch_bounds__(256) void attn2_kernel(
    const float2* __restrict__ QFs, const float2* __restrict__ KFs,
    float2* __restrict__ OFs,
    const float2* __restrict__ QFd, const float2* __restrict__ KFd,
    float2* __restrict__ OFd, int m)
{
    __shared__ float2 qf[1024], kf[1024], S[256];
    int bh = blockIdx.x & 127, pair = blockIdx.x >> 7;
    int tid = threadIdx.x;
    const float2* QF = pair ? QFd : QFs;
    const float2* KF = pair ? KFd : KFs;
    float2* OF = pair ? OFd : OFs;
    const float2* qsrc = QF + (long)bh * 1024;
    const float2* ksrc = KF + (long)bh * 1024;
    for (int i = tid; i < 1024; i += 256) { qf[i] = qsrc[i]; kf[i] = ksrc[i]; }
    __syncthreads();

    for (int s = tid; s < m * m; s += 256) {
        int xx = s / m, yy = s - xx * m;
        float re = 0.f, im = 0.f;
#pragma unroll 8
        for (int e = 0; e < 64; e++) {
            float2 qv = qf[e * 16 + xx], kv = kf[e * 16 + yy];
            re += qv.x * kv.x - qv.y * kv.y;
            im += qv.x * kv.y + qv.y * kv.x;
        }
        float X = 2.f * re, Y = 2.f * im, orr, oii;
        if (fabsf(X) > 20.f) {
            orr = copysignf(1.f, X); oii = 0.f;
        } else {
            float ex = expf(X), enx = 1.f / ex;
            float sh = 0.5f * (ex - enx), ch = 0.5f * (ex + enx);
            float sy, cy; sincosf(Y, &sy, &cy);
            float den = ch + cy;
            orr = sh / den; oii = sy / den;
        }
        S[xx * 16 + yy] = make_float2(orr, oii);
    }
    __syncthreads();
    for (int o = tid; o < 64 * m; o += 256) {
        int e = o / m, xx = o - e * m;
        float re = 0.f, im = 0.f;
        for (int yy = 0; yy < m; yy++) {
            float2 sv = S[xx * 16 + yy], kv = kf[e * 16 + yy];
            re += sv.x * kv.x - sv.y * kv.y;
            im += sv.x * kv.y + sv.y * kv.x;
        }
        OF[(long)bh * 1024 + e * 16 + xx] = make_float2(re, im);
    }
}

// ---------------------------------------------------------------------------
// irfft x2 — float2 twiddles + of_s hoisted to registers (el fixed per thread)
// ---------------------------------------------------------------------------
__global__ __launch_bounds__(256) void irfft2_kernel(
    const float2* __restrict__ OFs, const float2* __restrict__ OFd,
    float* __restrict__ US, float* __restrict__ UD, int L, int m)
{
    __shared__ float2 tw[512];
    __shared__ float2 of_s[64][16];
    int tid = threadIdx.x, ec = blockIdx.x, b = blockIdx.y, z = blockIdx.z;
    float* out = z ? UD : US;

    for (int i = tid; i < L; i += 256) {
        float th = 6.2831853071795864f * (float)i / (float)L;
        float s, c; sincosf(th, &s, &c);
        tw[i] = make_float2(c, s);
    }
    float inv = 1.f / ((float)L * 4096.f);
    for (int i = tid; i < 1024; i += 256) {
        int el = i >> 4, xx = i & 15;
        int e = ec * 8 + (el >> 3), h = el & 7;
        float2 v = make_float2(0.f, 0.f);
        if (xx < m) {
            long src = ((long)((b * 8 + h) * 64 + e)) * 16 + xx;
            v = OFs[src];
            if (z) { float2 d = OFd[src]; v.x += d.x; v.y += d.y; }
        }
        float w = (xx == 0) ? inv : 2.f * inv;
        of_s[el][xx] = make_float2(v.x * w, v.y * w);
    }
    __syncthreads();

    // el = (i & 63) with stride-256 i-loop => constant per thread. Hoist.
    const int el = tid & 63;
    float2 of[16];
#pragma unroll
    for (int xx = 0; xx < 16; xx++) of[xx] = of_s[el][xx];

    for (long i = tid; i < (long)L * 64; i += 256) {
        int t = (int)(i >> 6);
        float acc = 0.f;
#pragma unroll
        for (int xx = 0; xx < 16; xx++) {
            int id = (xx * t) & (L - 1);
            float2 w = tw[id];
            acc += of[xx].x * w.x - of[xx].y * w.y;
        }
        long dst = ((long)(b * L + t)) * CKD + ec * 64 + el;
        out[dst] = acc;
    }
}

__global__ void zero2_kernel(float* p0, float* p1, long n) {
    long i = (long)blockIdx.x * blockDim.x + threadIdx.x;
    if (i < n) { p0[i] = 0.f; p1[i] = 0.f; }
}

// ---------------------------------------------------------------------------
extern "C" void kernel_launch(void* const* d_in, const int* in_sizes, int n_in,
                              void* d_out, int out_size)
{
    const float* q    = (const float*)d_in[0];
    const float* k    = (const float*)d_in[1];
    const float* Lq_w = (const float*)d_in[3];
    const float* Lq_b = (const float*)d_in[4];
    const float* Lk_w = (const float*)d_in[5];
    const float* Lk_b = (const float*)d_in[6];
    const float* out_w = (const float*)d_in[9];
    const float* out_b = (const float*)d_in[10];
    const float* ec_s = (const float*)d_in[11];
    const float* ec_d = (const float*)d_in[12];
    const float* rc_e = (const float*)d_in[13];
    const float* rc_o = (const float*)d_in[14];

    float *QA, *QB, *KA, *KB, *DQ, *DK, *US, *UD, *VA, *VB;
    float2 *QFs, *KFs, *QFd, *KFd, *OFs, *OFd;
    __nv_bfloat16 *Ah, *Al, *Ah2, *Al2, *Wh0, *Wl0, *Wh1, *Wl1, *Wh2, *Wl2;
    cudaGetSymbolAddress((void**)&QA, g_QA);
    cudaGetSymbolAddress((void**)&QB, g_QB);
    cudaGetSymbolAddress((void**)&KA, g_KA);
    cudaGetSymbolAddress((void**)&KB, g_KB);
    cudaGetSymbolAddress((void**)&DQ, g_DQ);
    cudaGetSymbolAddress((void**)&DK, g_DK);
    cudaGetSymbolAddress((void**)&US, g_US);
    cudaGetSymbolAddress((void**)&UD, g_UD);
    cudaGetSymbolAddress((void**)&VA, g_VA);
    cudaGetSymbolAddress((void**)&VB, g_VB);
    cudaGetSymbolAddress((void**)&QFs, g_QFs);
    cudaGetSymbolAddress((void**)&KFs, g_KFs);
    cudaGetSymbolAddress((void**)&QFd, g_QFd);
    cudaGetSymbolAddress((void**)&KFd, g_KFd);
    cudaGetSymbolAddress((void**)&OFs, g_OFs);
    cudaGetSymbolAddress((void**)&OFd, g_OFd);
    cudaGetSymbolAddress((void**)&Ah, g_Ah);
    cudaGetSymbolAddress((void**)&Al, g_Al);
    cudaGetSymbolAddress((void**)&Ah2, g_Ah2);
    cudaGetSymbolAddress((void**)&Al2, g_Al2);
    cudaGetSymbolAddress((void**)&Wh0, g_Wh0);
    cudaGetSymbolAddress((void**)&Wl0, g_Wl0);
    cudaGetSymbolAddress((void**)&Wh1, g_Wh1);
    cudaGetSymbolAddress((void**)&Wl1, g_Wl1);
    cudaGetSymbolAddress((void**)&Wh2, g_Wh2);
    cudaGetSymbolAddress((void**)&Wl2, g_Wl2);

    cudaFuncSetAttribute(gemm_bf16x3,
                         cudaFuncAttributeMaxDynamicSharedMemorySize,
                         GSMEM_BYTES);
    cudaFuncSetAttribute(gemm_bf16x3_dual,
                         cudaFuncAttributeMaxDynamicSharedMemorySize,
                         GSMEM_BYTES);

    // weight splits (all three) + input splits (q,k) + dual projection GEMM
    split_wt3_kernel<<<dim3(16, 16, 3), dim3(32, 8)>>>(
        Lq_w, Lk_w, out_w, Wh0, Wl0, Wh1, Wl1, Wh2, Wl2);
    split_a2_kernel<<<dim3(8192, 2), 256>>>(q, k, Ah, Al, Ah2, Al2, 2097152);
    gemm_bf16x3_dual<<<dim3(4, 128, 2), 256, GSMEM_BYTES>>>(
        Ah, Al, Wh0, Wl0, Lq_b, QA,
        Ah2, Al2, Wh1, Wl1, Lk_b, KA);

    float* qc = QA; float* qn = QB;
    float* kc = KA; float* kn = KB;
    long offs[10]; int Lhs[10];
    long off = 0;
    int L = 1024;
    for (int i = 0; i < 10; i++) {
        int Lh = L >> 1;
        Lhs[i] = Lh; offs[i] = off;
        off += (long)BB * Lh * CKD;
        int m = (Lh / 2 < 16) ? (Lh / 2) : 16;
        long total = (long)BB * Lh * 64;
        int blocks = (int)((total + 255) / 256);

        wavelet2_kernel<<<dim3(blocks, 2), 256>>>(
            qc, kc, ec_d, ec_s, DQ, qn, DK, kn, Lh);

        long sz = (long)BB * Lh * CKD;
        if (m > 0) {
            rfft4_kernel<<<dim3(8, BB, 4), 256>>>(
                DQ, DK, qn, kn, QFs, KFs, QFd, KFd, Lh, m);
            attn2_kernel<<<256, 256>>>(QFs, KFs, OFs, QFd, KFd, OFd, m);
            irfft2_kernel<<<dim3(8, BB, 2), 256>>>(
                OFs, OFd, US + offs[i], UD + offs[i], Lh, m);
        } else {
            zero2_kernel<<<(int)((sz + 255) / 256), 256>>>(
                US + offs[i], UD + offs[i], sz);
        }
        { float* t = qc; qc = qn; qn = t; }
        { float* t = kc; kc = kn; kn = t; }
        L = Lh;
    }

    zero2_kernel<<<32, 256>>>(VA, VA, (long)BB * 1 * CKD);
    float* vc = VA; float* vn = VB;
    for (int i = 9; i >= 0; i--) {
        int Lv = Lhs[i];
        long total = (long)BB * Lv * 64;
        recon_kernel<<<(int)((total + 255) / 256), 256>>>(
            vc, US + offs[i], UD + offs[i], rc_e, rc_o, vn, Lv,
            Ah, Al, (i == 0) ? 1 : 0);
        float* t = vc; vc = vn; vn = t;
    }

    // Output projection (recon already emitted the bf16 split into Ah/Al)
    gemm_bf16x3<<<dim3(4, 128), 256, GSMEM_BYTES>>>(
        Ah, Al, Wh2, Wl2, out_b, (float*)d_out);
}

// round 16
// speedup vs baseline: 2.0743x; 1.0330x over previous
#include <cuda_runtime.h>
#include <cuda_bf16.h>
#include <math.h>
#include <cstdint>

// ---------------------------------------------------------------------------
// MultiWaveletCross on GB300 — round 14: round-13 (825us) + PDL on all nodes
// (programmatic stream serialization; griddepcontrol.wait at kernel entry)
// ---------------------------------------------------------------------------

#define BB 16
#define CKD 512
#define NTOK 16384

#define PDL_WAIT() asm volatile("griddepcontrol.wait;" ::: "memory")

__device__ float g_QA[8388608];
__device__ float g_QB[8388608];
__device__ float g_KA[8388608];
__device__ float g_KB[8388608];
__device__ float g_DQ[4194304];
__device__ float g_DK[4194304];
__device__ float g_US[8380416];
__device__ float g_UD[8380416];
__device__ float g_VA[8388608];
__device__ float g_VB[8388608];
__device__ float2 g_QFs[131072];
__device__ float2 g_KFs[131072];
__device__ float2 g_QFd[131072];
__device__ float2 g_KFd[131072];
__device__ float2 g_OFs[131072];
__device__ float2 g_OFd[131072];
// bf16 split scratch
__device__ __nv_bfloat16 g_Ah[8388608];
__device__ __nv_bfloat16 g_Al[8388608];
__device__ __nv_bfloat16 g_Ah2[8388608];
__device__ __nv_bfloat16 g_Al2[8388608];
__device__ __nv_bfloat16 g_Wh0[262144];
__device__ __nv_bfloat16 g_Wl0[262144];
__device__ __nv_bfloat16 g_Wh1[262144];
__device__ __nv_bfloat16 g_Wl1[262144];
__device__ __nv_bfloat16 g_Wh2[262144];
__device__ __nv_bfloat16 g_Wl2[262144];

__device__ __forceinline__ uint32_t smem_to_u32(const void* p) {
    uint32_t a;
    asm("{ .reg .u64 t; cvta.to.shared.u64 t, %1; cvt.u32.u64 %0, t; }"
        : "=r"(a) : "l"(p));
    return a;
}

// ---------------------------------------------------------------------------
// split kernels
// ---------------------------------------------------------------------------
__device__ __forceinline__ void split_store4(
    __nv_bfloat16* h, __nv_bfloat16* l, long i, float4 v)
{
    __nv_bfloat16 h0 = __float2bfloat16(v.x);
    __nv_bfloat16 h1 = __float2bfloat16(v.y);
    __nv_bfloat16 h2 = __float2bfloat16(v.z);
    __nv_bfloat16 h3 = __float2bfloat16(v.w);
    __nv_bfloat16 l0 = __float2bfloat16(v.x - __bfloat162float(h0));
    __nv_bfloat16 l1 = __float2bfloat16(v.y - __bfloat162float(h1));
    __nv_bfloat16 l2 = __float2bfloat16(v.z - __bfloat162float(h2));
    __nv_bfloat16 l3 = __float2bfloat16(v.w - __bfloat162float(h3));
    __nv_bfloat162* hp = (__nv_bfloat162*)(h + i * 4);
    __nv_bfloat162* lp = (__nv_bfloat162*)(l + i * 4);
    hp[0] = __nv_bfloat162(h0, h1); hp[1] = __nv_bfloat162(h2, h3);
    lp[0] = __nv_bfloat162(l0, l1); lp[1] = __nv_bfloat162(l2, l3);
}

__global__ __launch_bounds__(256) void split_a2_kernel(
    const float* __restrict__ x0, const float* __restrict__ x1,
    __nv_bfloat16* __restrict__ h0, __nv_bfloat16* __restrict__ l0,
    __nv_bfloat16* __restrict__ h1, __nv_bfloat16* __restrict__ l1,
    long n4)
{
    PDL_WAIT();
    long i = (long)blockIdx.x * 256 + threadIdx.x;
    if (i >= n4) return;
    const float* x = blockIdx.y ? x1 : x0;
    __nv_bfloat16* h = blockIdx.y ? h1 : h0;
    __nv_bfloat16* l = blockIdx.y ? l1 : l0;
    split_store4(h, l, i, *(const float4*)(x + i * 4));
}

__global__ __launch_bounds__(256) void split_wt3_kernel(
    const float* __restrict__ W0, const float* __restrict__ W1,
    const float* __restrict__ W2,
    __nv_bfloat16* __restrict__ h0, __nv_bfloat16* __restrict__ l0,
    __nv_bfloat16* __restrict__ h1, __nv_bfloat16* __restrict__ l1,
    __nv_bfloat16* __restrict__ h2, __nv_bfloat16* __restrict__ l2)
{
    __shared__ float t[32][33];
    PDL_WAIT();
    int tx = threadIdx.x, ty = threadIdx.y;
    int bx = blockIdx.x, by = blockIdx.y, bz = blockIdx.z;
    const float* W = bz == 0 ? W0 : (bz == 1 ? W1 : W2);
    __nv_bfloat16* hT = bz == 0 ? h0 : (bz == 1 ? h1 : h2);
    __nv_bfloat16* lT = bz == 0 ? l0 : (bz == 1 ? l1 : l2);
#pragma unroll
    for (int j = 0; j < 4; j++)
        t[ty + 8 * j][tx] = W[(size_t)(by * 32 + ty + 8 * j) * 512 + bx * 32 + tx];
    __syncthreads();
#pragma unroll
    for (int j = 0; j < 4; j++) {
        float v = t[tx][ty + 8 * j];
        int n_o = bx * 32 + ty + 8 * j;
        int k_o = by * 32 + tx;
        __nv_bfloat16 hb = __float2bfloat16(v);
        __nv_bfloat16 lb = __float2bfloat16(v - __bfloat162float(hb));
        hT[(size_t)n_o * 512 + k_o] = hb;
        lT[(size_t)n_o * 512 + k_o] = lb;
    }
}

// ---------------------------------------------------------------------------
// bf16x3 GEMM core
// ---------------------------------------------------------------------------
#define LDAE 40
#define ARR_B (128 * LDAE * 2)
#define BUF_B (4 * ARR_B)
#define GSMEM_BYTES (2 * BUF_B)

#define CP_ASYNC16(dst, src) \
    asm volatile("cp.async.cg.shared.global [%0], [%1], 16;" \
        :: "r"(dst), "l"(src))
#define CP_COMMIT() asm volatile("cp.async.commit_group;" ::: "memory")
#define CP_WAIT1() asm volatile("cp.async.wait_group 1;" ::: "memory")
#define CP_WAIT0() asm volatile("cp.async.wait_group 0;" ::: "memory")

#define LDSM_X4(R, addr) \
    asm volatile("ldmatrix.sync.aligned.m8n8.x4.shared.b16 {%0,%1,%2,%3}, [%4];" \
        : "=r"((R)[0]), "=r"((R)[1]), "=r"((R)[2]), "=r"((R)[3]) : "r"(addr))
#define LDSM_X2(R, addr) \
    asm volatile("ldmatrix.sync.aligned.m8n8.x2.shared.b16 {%0,%1}, [%2];" \
        : "=r"((R)[0]), "=r"((R)[1]) : "r"(addr))

#define MMA_BF16(ACC, A, B0, B1) \
    asm volatile( \
        "mma.sync.aligned.m16n8k16.row.col.f32.bf16.bf16.f32 " \
        "{%0,%1,%2,%3}, {%4,%5,%6,%7}, {%8,%9}, {%0,%1,%2,%3};" \
        : "+f"((ACC)[0]), "+f"((ACC)[1]), "+f"((ACC)[2]), "+f"((ACC)[3]) \
        : "r"((A)[0]), "r"((A)[1]), "r"((A)[2]), "r"((A)[3]), \
          "r"(B0), "r"(B1))

__device__ __forceinline__ void gemm_core(
    char* dsm,
    const __nv_bfloat16* __restrict__ Ah, const __nv_bfloat16* __restrict__ Al,
    const __nv_bfloat16* __restrict__ Bh, const __nv_bfloat16* __restrict__ Bl,
    const float* __restrict__ bias, float* __restrict__ C)
{
    const int tid = threadIdx.x;
    const int wid = tid >> 5, lane = tid & 31;
    const int bm = blockIdx.y * 128, bn = blockIdx.x * 128;
    const int wm = (wid >> 2) * 64, wn = (wid & 3) * 32;
    const int lr = lane >> 2, lc = lane & 3;
    const uint32_t sb = smem_to_u32(dsm);

    float acc[4][4][4];
#pragma unroll
    for (int mi = 0; mi < 4; mi++)
#pragma unroll
        for (int ni = 0; ni < 4; ni++)
#pragma unroll
            for (int r = 0; r < 4; r++) acc[mi][ni][r] = 0.f;

    const __nv_bfloat16* gsrc0 = Ah + (size_t)bm * 512;
    const __nv_bfloat16* gsrc1 = Al + (size_t)bm * 512;
    const __nv_bfloat16* gsrc2 = Bh + (size_t)bn * 512;
    const __nv_bfloat16* gsrc3 = Bl + (size_t)bn * 512;

    const int pc0 = tid, pc1 = tid + 256;
    const int pr0 = pc0 >> 2, po0 = (pc0 & 3);
    const int pr1 = pc1 >> 2, po1 = (pc1 & 3);

#define PRODUCE(KB, BUF) do {                                                  \
    uint32_t base = sb + (BUF) * BUF_B;                                        \
    int kg = (KB) * 32;                                                        \
    CP_ASYNC16(base + pr0 * 80 + po0 * 16,                                     \
               gsrc0 + (size_t)pr0 * 512 + kg + po0 * 8);                      \
    CP_ASYNC16(base + pr1 * 80 + po1 * 16,                                     \
               gsrc0 + (size_t)pr1 * 512 + kg + po1 * 8);                      \
    CP_ASYNC16(base + ARR_B + pr0 * 80 + po0 * 16,                             \
               gsrc1 + (size_t)pr0 * 512 + kg + po0 * 8);                      \
    CP_ASYNC16(base + ARR_B + pr1 * 80 + po1 * 16,                             \
               gsrc1 + (size_t)pr1 * 512 + kg + po1 * 8);                      \
    CP_ASYNC16(base + 2 * ARR_B + pr0 * 80 + po0 * 16,                         \
               gsrc2 + (size_t)pr0 * 512 + kg + po0 * 8);                      \
    CP_ASYNC16(base + 2 * ARR_B + pr1 * 80 + po1 * 16,                         \
               gsrc2 + (size_t)pr1 * 512 + kg + po1 * 8);                      \
    CP_ASYNC16(base + 3 * ARR_B + pr0 * 80 + po0 * 16,                         \
               gsrc3 + (size_t)pr0 * 512 + kg + po0 * 8);                      \
    CP_ASYNC16(base + 3 * ARR_B + pr1 * 80 + po1 * 16,                         \
               gsrc3 + (size_t)pr1 * 512 + kg + po1 * 8);                      \
    CP_COMMIT();                                                               \
} while (0)

    const int a_row_off = (lane & 7) + ((lane >> 3) & 1) * 8;
    const int a_k_off = (lane >> 4) * 8;
    const int b_row_off = lane & 7;
    const int b_k_off = ((lane >> 3) & 1) * 8;

    PRODUCE(0, 0);
    for (int kb = 0; kb < 16; kb++) {
        if (kb < 15) PRODUCE(kb + 1, (kb + 1) & 1);
        if (kb < 15) { CP_WAIT1(); } else { CP_WAIT0(); }
        __syncthreads();
        const uint32_t base = sb + (kb & 1) * BUF_B;

#pragma unroll
        for (int k16 = 0; k16 < 32; k16 += 16) {
            uint32_t ah[4][4], al[4][4], bh[4][2], bl[4][2];
#pragma unroll
            for (int mi = 0; mi < 4; mi++) {
                uint32_t addr = base +
                    ((wm + mi * 16 + a_row_off) * LDAE + k16 + a_k_off) * 2;
                LDSM_X4(ah[mi], addr);
                LDSM_X4(al[mi], addr + ARR_B);
            }
#pragma unroll
            for (int ni = 0; ni < 4; ni++) {
                uint32_t addr = base + 2 * ARR_B +
                    ((wn + ni * 8 + b_row_off) * LDAE + k16 + b_k_off) * 2;
                LDSM_X2(bh[ni], addr);
                LDSM_X2(bl[ni], addr + ARR_B);
            }
#pragma unroll
            for (int mi = 0; mi < 4; mi++)
#pragma unroll
                for (int ni = 0; ni < 4; ni++) {
                    MMA_BF16(acc[mi][ni], ah[mi], bh[ni][0], bh[ni][1]);
                    MMA_BF16(acc[mi][ni], ah[mi], bl[ni][0], bl[ni][1]);
                    MMA_BF16(acc[mi][ni], al[mi], bh[ni][0], bh[ni][1]);
                }
        }
        __syncthreads();
    }

#pragma unroll
    for (int mi = 0; mi < 4; mi++) {
#pragma unroll
        for (int ni = 0; ni < 4; ni++) {
            int col = bn + wn + ni * 8 + 2 * lc;
            float2 bv = *(const float2*)(bias + col);
            int r0 = bm + wm + mi * 16 + lr;
            float2 o0 = make_float2(acc[mi][ni][0] + bv.x, acc[mi][ni][1] + bv.y);
            float2 o1 = make_float2(acc[mi][ni][2] + bv.x, acc[mi][ni][3] + bv.y);
            *(float2*)(C + (size_t)r0 * 512 + col) = o0;
            *(float2*)(C + (size_t)(r0 + 8) * 512 + col) = o1;
        }
    }
#undef PRODUCE
}

__global__ __launch_bounds__(256, 2) void gemm_bf16x3(
    const __nv_bfloat16* __restrict__ Ah, const __nv_bfloat16* __restrict__ Al,
    const __nv_bfloat16* __restrict__ Bh, const __nv_bfloat16* __restrict__ Bl,
    const float* __restrict__ bias, float* __restrict__ C)
{
    extern __shared__ __align__(16) char dsm[];
    PDL_WAIT();
    gemm_core(dsm, Ah, Al, Bh, Bl, bias, C);
}

__global__ __launch_bounds__(256, 2) void gemm_bf16x3_dual(
    const __nv_bfloat16* __restrict__ Ah0, const __nv_bfloat16* __restrict__ Al0,
    const __nv_bfloat16* __restrict__ Bh0, const __nv_bfloat16* __restrict__ Bl0,
    const float* __restrict__ b0, float* __restrict__ C0,
    const __nv_bfloat16* __restrict__ Ah1, const __nv_bfloat16* __restrict__ Al1,
    const __nv_bfloat16* __restrict__ Bh1, const __nv_bfloat16* __restrict__ Bl1,
    const float* __restrict__ b1, float* __restrict__ C1)
{
    extern __shared__ __align__(16) char dsm[];
    PDL_WAIT();
    if (blockIdx.z == 0)
        gemm_core(dsm, Ah0, Al0, Bh0, Bl0, b0, C0);
    else
        gemm_core(dsm, Ah1, Al1, Bh1, Bl1, b1, C1);
}

// ---------------------------------------------------------------------------
// Wavelet step — q and k in one launch
// ---------------------------------------------------------------------------
__global__ __launch_bounds__(256) void wavelet2_kernel(
    const float* __restrict__ xq, const float* __restrict__ xk,
    const float* __restrict__ ecd, const float* __restrict__ ecs,
    float* __restrict__ dq, float* __restrict__ qn,
    float* __restrict__ dk, float* __restrict__ kn, int Lh)
{
    __shared__ float wd[16][8], ws_[16][8];
    PDL_WAIT();
    int tid = threadIdx.x;
    if (tid < 128)       wd[tid >> 3][tid & 7] = ecd[tid];
    else if (tid < 256)  { int t = tid - 128; ws_[t >> 3][t & 7] = ecs[t]; }
    __syncthreads();

    const float* x = blockIdx.y ? xk : xq;
    float* od = blockIdx.y ? dk : dq;
    float* os = blockIdx.y ? kn : qn;

    long idx = (long)blockIdx.x * 256 + tid;
    long total = (long)BB * Lh * 64;
    if (idx >= total) return;
    int c = (int)(idx & 63);
    long bt = idx >> 6;
    int t2 = (int)(bt % Lh);
    int b = (int)(bt / Lh);

    const float* p0 = x + ((long)(b * 2 * Lh + 2 * t2)) * CKD + c * 8;
    float a[16];
    *(float4*)(a)      = *(const float4*)(p0);
    *(float4*)(a + 4)  = *(const float4*)(p0 + 4);
    *(float4*)(a + 8)  = *(const float4*)(p0 + CKD);
    *(float4*)(a + 12) = *(const float4*)(p0 + CKD + 4);

    float rd[8], rs[8];
#pragma unroll
    for (int kk = 0; kk < 8; kk++) { rd[kk] = 0.f; rs[kk] = 0.f; }
#pragma unroll
    for (int j = 0; j < 16; j++)
#pragma unroll
        for (int kk = 0; kk < 8; kk++) {
            rd[kk] += a[j] * wd[j][kk];
            rs[kk] += a[j] * ws_[j][kk];
        }
    float* pd = od + ((long)(b * Lh + t2)) * CKD + c * 8;
    float* ps = os + ((long)(b * Lh + t2)) * CKD + c * 8;
    *(float4*)(pd)     = *(float4*)(rd);
    *(float4*)(pd + 4) = *(float4*)(rd + 4);
    *(float4*)(ps)     = *(float4*)(rs);
    *(float4*)(ps + 4) = *(float4*)(rs + 4);
}

// ---------------------------------------------------------------------------
// Reconstruction step (optionally emits bf16 hi/lo split)
// ---------------------------------------------------------------------------
__global__ __launch_bounds__(256) void recon_kernel(
    const float* __restrict__ vin, const float* __restrict__ us,
    const float* __restrict__ ud, const float* __restrict__ rce,
    const float* __restrict__ rco, float* __restrict__ vout, int Lv,
    __nv_bfloat16* __restrict__ oh, __nv_bfloat16* __restrict__ ol,
    int do_split)
{
    __shared__ float we[16][8], wo[16][8];
    PDL_WAIT();
    int tid = threadIdx.x;
    if (tid < 128)       we[tid >> 3][tid & 7] = rce[tid];
    else if (tid < 256)  { int t = tid - 128; wo[t >> 3][t & 7] = rco[t]; }
    __syncthreads();

    long idx = (long)blockIdx.x * 256 + tid;
    long total = (long)BB * Lv * 64;
    if (idx >= total) return;
    int c = (int)(idx & 63);
    long bt = idx >> 6;
    int t = (int)(bt % Lv);
    int b = (int)(bt / Lv);

    long base = ((long)(b * Lv + t)) * CKD + c * 8;
    float a[16];
#pragma unroll
    for (int j = 0; j < 8; j++) a[j] = vin[base + j] + us[base + j];
    *(float4*)(a + 8)  = *(const float4*)(ud + base);
    *(float4*)(a + 12) = *(const float4*)(ud + base + 4);

    float re[8], ro[8];
#pragma unroll
    for (int kk = 0; kk < 8; kk++) { re[kk] = 0.f; ro[kk] = 0.f; }
#pragma unroll
    for (int j = 0; j < 16; j++)
#pragma unroll
        for (int kk = 0; kk < 8; kk++) {
            re[kk] += a[j] * we[j][kk];
            ro[kk] += a[j] * wo[j][kk];
        }
    long obase = ((long)(b * 2 * Lv + 2 * t)) * CKD + c * 8;
    float* pe = vout + obase;
    *(float4*)(pe)           = *(float4*)(re);
    *(float4*)(pe + 4)       = *(float4*)(re + 4);
    *(float4*)(pe + CKD)     = *(float4*)(ro);
    *(float4*)(pe + CKD + 4) = *(float4*)(ro + 4);

    if (do_split) {
        split_store4(oh, ol, (obase >> 2),           *(float4*)(re));
        split_store4(oh, ol, (obase >> 2) + 1,       *(float4*)(re + 4));
        split_store4(oh, ol, ((obase + CKD) >> 2),     *(float4*)(ro));
        split_store4(oh, ol, ((obase + CKD) >> 2) + 1, *(float4*)(ro + 4));
    }
}

// ---------------------------------------------------------------------------
// rfft x4 streams — float2 twiddles
// ---------------------------------------------------------------------------
__global__ __launch_bounds__(256) void rfft4_kernel(
    const float* __restrict__ s0, const float* __restrict__ s1,
    const float* __restrict__ s2, const float* __restrict__ s3,
    float2* __restrict__ F0, float2* __restrict__ F1,
    float2* __restrict__ F2, float2* __restrict__ F3,
    int L, int m)
{
    __shared__ float2 tw[512];
    __shared__ float tile[64][64];
    PDL_WAIT();
    int tid = threadIdx.x;
    int ec = blockIdx.x;
    int b = blockIdx.y;
    int z = blockIdx.z;
    const float* x = z == 0 ? s0 : (z == 1 ? s1 : (z == 2 ? s2 : s3));
    float2* F = z == 0 ? F0 : (z == 1 ? F1 : (z == 2 ? F2 : F3));

    for (int i = tid; i < L; i += 256) {
        float th = 6.2831853071795864f * (float)i / (float)L;
        float s, c; sincosf(th, &s, &c);
        tw[i] = make_float2(c, s);
    }

    int eh = tid >> 2;
    int xg = tid & 3;
    float ar[4] = {0.f, 0.f, 0.f, 0.f}, ai[4] = {0.f, 0.f, 0.f, 0.f};

    for (int t0 = 0; t0 < L; t0 += 64) {
        int tc = L - t0 < 64 ? L - t0 : 64;
        __syncthreads();
        for (int i = tid; i < tc * 64; i += 256) {
            int tt = i >> 6, el = i & 63;
            tile[tt][el] = x[((long)(b * L + t0 + tt)) * CKD + ec * 64 + el];
        }
        __syncthreads();
        for (int tt = 0; tt < tc; tt++) {
            float v = tile[tt][eh];
            int t = t0 + tt;
#pragma unroll
            for (int j = 0; j < 4; j++) {
                int xx = xg + j * 4;
                int id = (xx * t) & (L - 1);
                float2 w = tw[id];
                ar[j] += v * w.x;
                ai[j] -= v * w.y;
            }
        }
    }
    int e = ec * 8 + (eh >> 3), h = eh & 7;
    float2* dst = F + ((long)((b * 8 + h) * 64 + e)) * 16;
#pragma unroll
    for (int j = 0; j < 4; j++) {
        int xx = xg + j * 4;
        if (xx < m) dst[xx] = make_float2(ar[j], ai[j]);
    }
}

// ---------------------------------------------------------------------------
// attn x2 pairs
// ---------------------------------------------------------------------------
__global__ __launch_bounds__(256) void attn2_kernel(
    const float2* __restrict__ QFs, const float2* __restrict__ KFs,
    float2* __restrict__ OFs,
    const float2* __restrict__ QFd, const float2* __restrict__ KFd,
    float2* __restrict__ OFd, int m)
{
    __shared__ float2 qf[1024], kf[1024], S[256];
    PDL_WAIT();
    int bh = blockIdx.x & 127, pair = blockIdx.x >> 7;
    int tid = threadIdx.x;
    const float2* QF = pair ? QFd : QFs;
    const float2* KF = pair ? KFd : KFs;
    float2* OF = pair ? OFd : OFs;
    const float2* qsrc = QF + (long)bh * 1024;
    const float2* ksrc = KF + (long)bh * 1024;
    for (int i = tid; i < 1024; i += 256) { qf[i] = qsrc[i]; kf[i] = ksrc[i]; }
    __syncthreads();

    for (int s = tid; s < m * m; s += 256) {
        int xx = s / m, yy = s - xx * m;
        float re = 0.f, im = 0.f;
#pragma unroll 8
        for (int e = 0; e < 64; e++) {
            float2 qv = qf[e * 16 + xx], kv = kf[e * 16 + yy];
            re += qv.x * kv.x - qv.y * kv.y;
            im += qv.x * kv.y + qv.y * kv.x;
        }
        float X = 2.f * re, Y = 2.f * im, orr, oii;
        if (fabsf(X) > 20.f) {
            orr = copysignf(1.f, X); oii = 0.f;
        } else {
            float ex = expf(X), enx = 1.f / ex;
            float sh = 0.5f * (ex - enx), ch = 0.5f * (ex + enx);
            float sy, cy; sincosf(Y, &sy, &cy);
            float den = ch + cy;
            orr = sh / den; oii = sy / den;
        }
        S[xx * 16 + yy] = make_float2(orr, oii);
    }
    __syncthreads();
    for (int o = tid; o < 64 * m; o += 256) {
        int e = o / m, xx = o - e * m;
        float re = 0.f, im = 0.f;
        for (int yy = 0; yy < m; yy++) {
            float2 sv = S[xx * 16 + yy], kv = kf[e * 16 + yy];
            re += sv.x * kv.x - sv.y * kv.y;
            im += sv.x * kv.y + sv.y * kv.x;
        }
        OF[(long)bh * 1024 + e * 16 + xx] = make_float2(re, im);
    }
}

// ---------------------------------------------------------------------------
// irfft x2 — float2 twiddles + of_s hoisted to registers
// ---------------------------------------------------------------------------
__global__ __launch_bounds__(256) void irfft2_kernel(
    const float2* __restrict__ OFs, const float2* __restrict__ OFd,
    float* __restrict__ US, float* __restrict__ UD, int L, int m)
{
    __shared__ float2 tw[512];
    __shared__ float2 of_s[64][16];
    PDL_WAIT();
    int tid = threadIdx.x, ec = blockIdx.x, b = blockIdx.y, z = blockIdx.z;
    float* out = z ? UD : US;

    for (int i = tid; i < L; i += 256) {
        float th = 6.2831853071795864f * (float)i / (float)L;
        float s, c; sincosf(th, &s, &c);
        tw[i] = make_float2(c, s);
    }
    float inv = 1.f / ((float)L * 4096.f);
    for (int i = tid; i < 1024; i += 256) {
        int el = i >> 4, xx = i & 15;
        int e = ec * 8 + (el >> 3), h = el & 7;
        float2 v = make_float2(0.f, 0.f);
        if (xx < m) {
            long src = ((long)((b * 8 + h) * 64 + e)) * 16 + xx;
            v = OFs[src];
            if (z) { float2 d = OFd[src]; v.x += d.x; v.y += d.y; }
        }
        float w = (xx == 0) ? inv : 2.f * inv;
        of_s[el][xx] = make_float2(v.x * w, v.y * w);
    }
    __syncthreads();

    const int el = tid & 63;
    float2 of[16];
#pragma unroll
    for (int xx = 0; xx < 16; xx++) of[xx] = of_s[el][xx];

    for (long i = tid; i < (long)L * 64; i += 256) {
        int t = (int)(i >> 6);
        float acc = 0.f;
#pragma unroll
        for (int xx = 0; xx < 16; xx++) {
            int id = (xx * t) & (L - 1);
            float2 w = tw[id];
            acc += of[xx].x * w.x - of[xx].y * w.y;
        }
        long dst = ((long)(b * L + t)) * CKD + ec * 64 + el;
        out[dst] = acc;
    }
}

__global__ void zero2_kernel(float* p0, float* p1, long n) {
    PDL_WAIT();
    long i = (long)blockIdx.x * blockDim.x + threadIdx.x;
    if (i < n) { p0[i] = 0.f; p1[i] = 0.f; }
}

// ---------------------------------------------------------------------------
// PDL launch helper: programmatic stream serialization on every node
// ---------------------------------------------------------------------------
template <typename... Args>
static inline void pdl_launch(void (*kern)(Args...), dim3 g, dim3 b,
                              size_t smem, Args... args)
{
    cudaLaunchConfig_t cfg = {};
    cfg.gridDim = g;
    cfg.blockDim = b;
    cfg.dynamicSmemBytes = smem;
    cudaLaunchAttribute at[1];
    at[0].id = cudaLaunchAttributeProgrammaticStreamSerialization;
    at[0].val.programmaticStreamSerializationAllowed = 1;
    cfg.attrs = at;
    cfg.numAttrs = 1;
    cudaLaunchKernelEx(&cfg, kern, args...);
}

// ---------------------------------------------------------------------------
extern "C" void kernel_launch(void* const* d_in, const int* in_sizes, int n_in,
                              void* d_out, int out_size)
{
    const float* q    = (const float*)d_in[0];
    const float* k    = (const float*)d_in[1];
    const float* Lq_w = (const float*)d_in[3];
    const float* Lq_b = (const float*)d_in[4];
    const float* Lk_w = (const float*)d_in[5];
    const float* Lk_b = (const float*)d_in[6];
    const float* out_w = (const float*)d_in[9];
    const float* out_b = (const float*)d_in[10];
    const float* ec_s = (const float*)d_in[11];
    const float* ec_d = (const float*)d_in[12];
    const float* rc_e = (const float*)d_in[13];
    const float* rc_o = (const float*)d_in[14];

    float *QA, *QB, *KA, *KB, *DQ, *DK, *US, *UD, *VA, *VB;
    float2 *QFs, *KFs, *QFd, *KFd, *OFs, *OFd;
    __nv_bfloat16 *Ah, *Al, *Ah2, *Al2, *Wh0, *Wl0, *Wh1, *Wl1, *Wh2, *Wl2;
    cudaGetSymbolAddress((void**)&QA, g_QA);
    cudaGetSymbolAddress((void**)&QB, g_QB);
    cudaGetSymbolAddress((void**)&KA, g_KA);
    cudaGetSymbolAddress((void**)&KB, g_KB);
    cudaGetSymbolAddress((void**)&DQ, g_DQ);
    cudaGetSymbolAddress((void**)&DK, g_DK);
    cudaGetSymbolAddress((void**)&US, g_US);
    cudaGetSymbolAddress((void**)&UD, g_UD);
    cudaGetSymbolAddress((void**)&VA, g_VA);
    cudaGetSymbolAddress((void**)&VB, g_VB);
    cudaGetSymbolAddress((void**)&QFs, g_QFs);
    cudaGetSymbolAddress((void**)&KFs, g_KFs);
    cudaGetSymbolAddress((void**)&QFd, g_QFd);
    cudaGetSymbolAddress((void**)&KFd, g_KFd);
    cudaGetSymbolAddress((void**)&OFs, g_OFs);
    cudaGetSymbolAddress((void**)&OFd, g_OFd);
    cudaGetSymbolAddress((void**)&Ah, g_Ah);
    cudaGetSymbolAddress((void**)&Al, g_Al);
    cudaGetSymbolAddress((void**)&Ah2, g_Ah2);
    cudaGetSymbolAddress((void**)&Al2, g_Al2);
    cudaGetSymbolAddress((void**)&Wh0, g_Wh0);
    cudaGetSymbolAddress((void**)&Wl0, g_Wl0);
    cudaGetSymbolAddress((void**)&Wh1, g_Wh1);
    cudaGetSymbolAddress((void**)&Wl1, g_Wl1);
    cudaGetSymbolAddress((void**)&Wh2, g_Wh2);
    cudaGetSymbolAddress((void**)&Wl2, g_Wl2);

    cudaFuncSetAttribute(gemm_bf16x3,
                         cudaFuncAttributeMaxDynamicSharedMemorySize,
                         GSMEM_BYTES);
    cudaFuncSetAttribute(gemm_bf16x3_dual,
                         cudaFuncAttributeMaxDynamicSharedMemorySize,
                         GSMEM_BYTES);

    // weight splits (all three) + input splits (q,k) + dual projection GEMM
    pdl_launch(split_wt3_kernel, dim3(16, 16, 3), dim3(32, 8), 0,
               Lq_w, Lk_w, out_w, Wh0, Wl0, Wh1, Wl1, Wh2, Wl2);
    pdl_launch(split_a2_kernel, dim3(8192, 2), dim3(256), 0,
               q, k, Ah, Al, Ah2, Al2, (long)2097152);
    pdl_launch(gemm_bf16x3_dual, dim3(4, 128, 2), dim3(256), (size_t)GSMEM_BYTES,
               (const __nv_bfloat16*)Ah, (const __nv_bfloat16*)Al,
               (const __nv_bfloat16*)Wh0, (const __nv_bfloat16*)Wl0,
               Lq_b, QA,
               (const __nv_bfloat16*)Ah2, (const __nv_bfloat16*)Al2,
               (const __nv_bfloat16*)Wh1, (const __nv_bfloat16*)Wl1,
               Lk_b, KA);

    float* qc = QA; float* qn = QB;
    float* kc = KA; float* kn = KB;
    long offs[10]; int Lhs[10];
    long off = 0;
    int L = 1024;
    for (int i = 0; i < 10; i++) {
        int Lh = L >> 1;
        Lhs[i] = Lh; offs[i] = off;
        off += (long)BB * Lh * CKD;
        int m = (Lh / 2 < 16) ? (Lh / 2) : 16;
        long total = (long)BB * Lh * 64;
        int blocks = (int)((total + 255) / 256);

        pdl_launch(wavelet2_kernel, dim3(blocks, 2), dim3(256), 0,
                   (const float*)qc, (const float*)kc, ec_d, ec_s,
                   DQ, qn, DK, kn, Lh);

        long sz = (long)BB * Lh * CKD;
        if (m > 0) {
            pdl_launch(rfft4_kernel, dim3(8, BB, 4), dim3(256), 0,
                       (const float*)DQ, (const float*)DK,
                       (const float*)qn, (const float*)kn,
                       QFs, KFs, QFd, KFd, Lh, m);
            pdl_launch(attn2_kernel, dim3(256), dim3(256), 0,
                       (const float2*)QFs, (const float2*)KFs, OFs,
                       (const float2*)QFd, (const float2*)KFd, OFd, m);
            pdl_launch(irfft2_kernel, dim3(8, BB, 2), dim3(256), 0,
                       (const float2*)OFs, (const float2*)OFd,
                       US + offs[i], UD + offs[i], Lh, m);
        } else {
            pdl_launch(zero2_kernel, dim3((unsigned)((sz + 255) / 256)),
                       dim3(256), 0, US + offs[i], UD + offs[i], sz);
        }
        { float* t = qc; qc = qn; qn = t; }
        { float* t = kc; kc = kn; kn = t; }
        L = Lh;
    }

    pdl_launch(zero2_kernel, dim3(32), dim3(256), 0,
               VA, VA, (long)BB * 1 * CKD);
    float* vc = VA; float* vn = VB;
    for (int i = 9; i >= 0; i--) {
        int Lv = Lhs[i];
        long total = (long)BB * Lv * 64;
        pdl_launch(recon_kernel, dim3((unsigned)((total + 255) / 256)),
                   dim3(256), 0,
                   (const float*)vc, (const float*)(US + offs[i]),
                   (const float*)(UD + offs[i]), rc_e, rc_o, vn, Lv,
                   Ah, Al, (i == 0) ? 1 : 0);
        float* t = vc; vc = vn; vn = t;
    }

    // Output projection (recon already emitted the bf16 split into Ah/Al)
    pdl_launch(gemm_bf16x3, dim3(4, 128), dim3(256), (size_t)GSMEM_BYTES,
               (const __nv_bfloat16*)Ah, (const __nv_bfloat16*)Al,
               (const __nv_bfloat16*)Wh2, (const __nv_bfloat16*)Wl2,
               out_b, (float*)d_out);
}

// round 17
// speedup vs baseline: 2.2589x; 1.0890x over previous
#include <cuda_runtime.h>
#include <cuda_bf16.h>
#include <math.h>
#include <cstdint>

// ---------------------------------------------------------------------------
// MultiWaveletCross on GB300 — round 17: PDL + level-batched fca pipeline
// (one rfft_all / attn_all / irfft_all launch across all 9 fca levels)
// ---------------------------------------------------------------------------

#define BB 16
#define CKD 512
#define NTOK 16384

#define PDL_WAIT() asm volatile("griddepcontrol.wait;" ::: "memory")

__device__ float g_QA[8388608];
__device__ float g_KA[8388608];
// per-level pyramids (offsets offs[i] = 16*512*(1024 - (1024>>i)))
__device__ float g_QS[8380416];
__device__ float g_KS[8380416];
__device__ float g_DQp[8380416];
__device__ float g_DKp[8380416];
__device__ float g_US[8380416];
__device__ float g_UD[8380416];
__device__ float g_VA[8388608];
__device__ float g_VB[8388608];
// per-level F buffers: lvl * 131072
__device__ float2 g_QFs[1179648];
__device__ float2 g_KFs[1179648];
__device__ float2 g_QFd[1179648];
__device__ float2 g_KFd[1179648];
__device__ float2 g_OFs[1179648];
__device__ float2 g_OFd[1179648];
// bf16 split scratch
__device__ __nv_bfloat16 g_Ah[8388608];
__device__ __nv_bfloat16 g_Al[8388608];
__device__ __nv_bfloat16 g_Ah2[8388608];
__device__ __nv_bfloat16 g_Al2[8388608];
__device__ __nv_bfloat16 g_Wh0[262144];
__device__ __nv_bfloat16 g_Wl0[262144];
__device__ __nv_bfloat16 g_Wh1[262144];
__device__ __nv_bfloat16 g_Wl1[262144];
__device__ __nv_bfloat16 g_Wh2[262144];
__device__ __nv_bfloat16 g_Wl2[262144];

__device__ __forceinline__ uint32_t smem_to_u32(const void* p) {
    uint32_t a;
    asm("{ .reg .u64 t; cvta.to.shared.u64 t, %1; cvt.u32.u64 %0, t; }"
        : "=r"(a) : "l"(p));
    return a;
}

__device__ __forceinline__ long lvl_off(int lvl) {
    return (long)16 * 512 * (1024 - (1024 >> lvl));
}

// ---------------------------------------------------------------------------
// split kernels
// ---------------------------------------------------------------------------
__device__ __forceinline__ void split_store4(
    __nv_bfloat16* h, __nv_bfloat16* l, long i, float4 v)
{
    __nv_bfloat16 h0 = __float2bfloat16(v.x);
    __nv_bfloat16 h1 = __float2bfloat16(v.y);
    __nv_bfloat16 h2 = __float2bfloat16(v.z);
    __nv_bfloat16 h3 = __float2bfloat16(v.w);
    __nv_bfloat16 l0 = __float2bfloat16(v.x - __bfloat162float(h0));
    __nv_bfloat16 l1 = __float2bfloat16(v.y - __bfloat162float(h1));
    __nv_bfloat16 l2 = __float2bfloat16(v.z - __bfloat162float(h2));
    __nv_bfloat16 l3 = __float2bfloat16(v.w - __bfloat162float(h3));
    __nv_bfloat162* hp = (__nv_bfloat162*)(h + i * 4);
    __nv_bfloat162* lp = (__nv_bfloat162*)(l + i * 4);
    hp[0] = __nv_bfloat162(h0, h1); hp[1] = __nv_bfloat162(h2, h3);
    lp[0] = __nv_bfloat162(l0, l1); lp[1] = __nv_bfloat162(l2, l3);
}

__global__ __launch_bounds__(256) void split_a2_kernel(
    const float* __restrict__ x0, const float* __restrict__ x1,
    __nv_bfloat16* __restrict__ h0, __nv_bfloat16* __restrict__ l0,
    __nv_bfloat16* __restrict__ h1, __nv_bfloat16* __restrict__ l1,
    long n4)
{
    PDL_WAIT();
    long i = (long)blockIdx.x * 256 + threadIdx.x;
    if (i >= n4) return;
    const float* x = blockIdx.y ? x1 : x0;
    __nv_bfloat16* h = blockIdx.y ? h1 : h0;
    __nv_bfloat16* l = blockIdx.y ? l1 : l0;
    split_store4(h, l, i, *(const float4*)(x + i * 4));
}

__global__ __launch_bounds__(256) void split_wt3_kernel(
    const float* __restrict__ W0, const float* __restrict__ W1,
    const float* __restrict__ W2,
    __nv_bfloat16* __restrict__ h0, __nv_bfloat16* __restrict__ l0,
    __nv_bfloat16* __restrict__ h1, __nv_bfloat16* __restrict__ l1,
    __nv_bfloat16* __restrict__ h2, __nv_bfloat16* __restrict__ l2)
{
    __shared__ float t[32][33];
    PDL_WAIT();
    int tx = threadIdx.x, ty = threadIdx.y;
    int bx = blockIdx.x, by = blockIdx.y, bz = blockIdx.z;
    const float* W = bz == 0 ? W0 : (bz == 1 ? W1 : W2);
    __nv_bfloat16* hT = bz == 0 ? h0 : (bz == 1 ? h1 : h2);
    __nv_bfloat16* lT = bz == 0 ? l0 : (bz == 1 ? l1 : l2);
#pragma unroll
    for (int j = 0; j < 4; j++)
        t[ty + 8 * j][tx] = W[(size_t)(by * 32 + ty + 8 * j) * 512 + bx * 32 + tx];
    __syncthreads();
#pragma unroll
    for (int j = 0; j < 4; j++) {
        float v = t[tx][ty + 8 * j];
        int n_o = bx * 32 + ty + 8 * j;
        int k_o = by * 32 + tx;
        __nv_bfloat16 hb = __float2bfloat16(v);
        __nv_bfloat16 lb = __float2bfloat16(v - __bfloat162float(hb));
        hT[(size_t)n_o * 512 + k_o] = hb;
        lT[(size_t)n_o * 512 + k_o] = lb;
    }
}

// ---------------------------------------------------------------------------
// bf16x3 GEMM core
// ---------------------------------------------------------------------------
#define LDAE 40
#define ARR_B (128 * LDAE * 2)
#define BUF_B (4 * ARR_B)
#define GSMEM_BYTES (2 * BUF_B)

#define CP_ASYNC16(dst, src) \
    asm volatile("cp.async.cg.shared.global [%0], [%1], 16;" \
        :: "r"(dst), "l"(src))
#define CP_COMMIT() asm volatile("cp.async.commit_group;" ::: "memory")
#define CP_WAIT1() asm volatile("cp.async.wait_group 1;" ::: "memory")
#define CP_WAIT0() asm volatile("cp.async.wait_group 0;" ::: "memory")

#define LDSM_X4(R, addr) \
    asm volatile("ldmatrix.sync.aligned.m8n8.x4.shared.b16 {%0,%1,%2,%3}, [%4];" \
        : "=r"((R)[0]), "=r"((R)[1]), "=r"((R)[2]), "=r"((R)[3]) : "r"(addr))
#define LDSM_X2(R, addr) \
    asm volatile("ldmatrix.sync.aligned.m8n8.x2.shared.b16 {%0,%1}, [%2];" \
        : "=r"((R)[0]), "=r"((R)[1]) : "r"(addr))

#define MMA_BF16(ACC, A, B0, B1) \
    asm volatile( \
        "mma.sync.aligned.m16n8k16.row.col.f32.bf16.bf16.f32 " \
        "{%0,%1,%2,%3}, {%4,%5,%6,%7}, {%8,%9}, {%0,%1,%2,%3};" \
        : "+f"((ACC)[0]), "+f"((ACC)[1]), "+f"((ACC)[2]), "+f"((ACC)[3]) \
        : "r"((A)[0]), "r"((A)[1]), "r"((A)[2]), "r"((A)[3]), \
          "r"(B0), "r"(B1))

__device__ __forceinline__ void gemm_core(
    char* dsm,
    const __nv_bfloat16* __restrict__ Ah, const __nv_bfloat16* __restrict__ Al,
    const __nv_bfloat16* __restrict__ Bh, const __nv_bfloat16* __restrict__ Bl,
    const float* __restrict__ bias, float* __restrict__ C)
{
    const int tid = threadIdx.x;
    const int wid = tid >> 5, lane = tid & 31;
    const int bm = blockIdx.y * 128, bn = blockIdx.x * 128;
    const int wm = (wid >> 2) * 64, wn = (wid & 3) * 32;
    const int lr = lane >> 2, lc = lane & 3;
    const uint32_t sb = smem_to_u32(dsm);

    float acc[4][4][4];
#pragma unroll
    for (int mi = 0; mi < 4; mi++)
#pragma unroll
        for (int ni = 0; ni < 4; ni++)
#pragma unroll
            for (int r = 0; r < 4; r++) acc[mi][ni][r] = 0.f;

    const __nv_bfloat16* gsrc0 = Ah + (size_t)bm * 512;
    const __nv_bfloat16* gsrc1 = Al + (size_t)bm * 512;
    const __nv_bfloat16* gsrc2 = Bh + (size_t)bn * 512;
    const __nv_bfloat16* gsrc3 = Bl + (size_t)bn * 512;

    const int pc0 = tid, pc1 = tid + 256;
    const int pr0 = pc0 >> 2, po0 = (pc0 & 3);
    const int pr1 = pc1 >> 2, po1 = (pc1 & 3);

#define PRODUCE(KB, BUF) do {                                                  \
    uint32_t base = sb + (BUF) * BUF_B;                                        \
    int kg = (KB) * 32;                                                        \
    CP_ASYNC16(base + pr0 * 80 + po0 * 16,                                     \
               gsrc0 + (size_t)pr0 * 512 + kg + po0 * 8);                      \
    CP_ASYNC16(base + pr1 * 80 + po1 * 16,                                     \
               gsrc0 + (size_t)pr1 * 512 + kg + po1 * 8);                      \
    CP_ASYNC16(base + ARR_B + pr0 * 80 + po0 * 16,                             \
               gsrc1 + (size_t)pr0 * 512 + kg + po0 * 8);                      \
    CP_ASYNC16(base + ARR_B + pr1 * 80 + po1 * 16,                             \
               gsrc1 + (size_t)pr1 * 512 + kg + po1 * 8);                      \
    CP_ASYNC16(base + 2 * ARR_B + pr0 * 80 + po0 * 16,                         \
               gsrc2 + (size_t)pr0 * 512 + kg + po0 * 8);                      \
    CP_ASYNC16(base + 2 * ARR_B + pr1 * 80 + po1 * 16,                         \
               gsrc2 + (size_t)pr1 * 512 + kg + po1 * 8);                      \
    CP_ASYNC16(base + 3 * ARR_B + pr0 * 80 + po0 * 16,                         \
               gsrc3 + (size_t)pr0 * 512 + kg + po0 * 8);                      \
    CP_ASYNC16(base + 3 * ARR_B + pr1 * 80 + po1 * 16,                         \
               gsrc3 + (size_t)pr1 * 512 + kg + po1 * 8);                      \
    CP_COMMIT();                                                               \
} while (0)

    const int a_row_off = (lane & 7) + ((lane >> 3) & 1) * 8;
    const int a_k_off = (lane >> 4) * 8;
    const int b_row_off = lane & 7;
    const int b_k_off = ((lane >> 3) & 1) * 8;

    PRODUCE(0, 0);
    for (int kb = 0; kb < 16; kb++) {
        if (kb < 15) PRODUCE(kb + 1, (kb + 1) & 1);
        if (kb < 15) { CP_WAIT1(); } else { CP_WAIT0(); }
        __syncthreads();
        const uint32_t base = sb + (kb & 1) * BUF_B;

#pragma unroll
        for (int k16 = 0; k16 < 32; k16 += 16) {
            uint32_t ah[4][4], al[4][4], bh[4][2], bl[4][2];
#pragma unroll
            for (int mi = 0; mi < 4; mi++) {
                uint32_t addr = base +
                    ((wm + mi * 16 + a_row_off) * LDAE + k16 + a_k_off) * 2;
                LDSM_X4(ah[mi], addr);
                LDSM_X4(al[mi], addr + ARR_B);
            }
#pragma unroll
            for (int ni = 0; ni < 4; ni++) {
                uint32_t addr = base + 2 * ARR_B +
                    ((wn + ni * 8 + b_row_off) * LDAE + k16 + b_k_off) * 2;
                LDSM_X2(bh[ni], addr);
                LDSM_X2(bl[ni], addr + ARR_B);
            }
#pragma unroll
            for (int mi = 0; mi < 4; mi++)
#pragma unroll
                for (int ni = 0; ni < 4; ni++) {
                    MMA_BF16(acc[mi][ni], ah[mi], bh[ni][0], bh[ni][1]);
                    MMA_BF16(acc[mi][ni], ah[mi], bl[ni][0], bl[ni][1]);
                    MMA_BF16(acc[mi][ni], al[mi], bh[ni][0], bh[ni][1]);
                }
        }
        __syncthreads();
    }

#pragma unroll
    for (int mi = 0; mi < 4; mi++) {
#pragma unroll
        for (int ni = 0; ni < 4; ni++) {
            int col = bn + wn + ni * 8 + 2 * lc;
            float2 bv = *(const float2*)(bias + col);
            int r0 = bm + wm + mi * 16 + lr;
            float2 o0 = make_float2(acc[mi][ni][0] + bv.x, acc[mi][ni][1] + bv.y);
            float2 o1 = make_float2(acc[mi][ni][2] + bv.x, acc[mi][ni][3] + bv.y);
            *(float2*)(C + (size_t)r0 * 512 + col) = o0;
            *(float2*)(C + (size_t)(r0 + 8) * 512 + col) = o1;
        }
    }
#undef PRODUCE
}

__global__ __launch_bounds__(256, 2) void gemm_bf16x3(
    const __nv_bfloat16* __restrict__ Ah, const __nv_bfloat16* __restrict__ Al,
    const __nv_bfloat16* __restrict__ Bh, const __nv_bfloat16* __restrict__ Bl,
    const float* __restrict__ bias, float* __restrict__ C)
{
    extern __shared__ __align__(16) char dsm[];
    PDL_WAIT();
    gemm_core(dsm, Ah, Al, Bh, Bl, bias, C);
}

__global__ __launch_bounds__(256, 2) void gemm_bf16x3_dual(
    const __nv_bfloat16* __restrict__ Ah0, const __nv_bfloat16* __restrict__ Al0,
    const __nv_bfloat16* __restrict__ Bh0, const __nv_bfloat16* __restrict__ Bl0,
    const float* __restrict__ b0, float* __restrict__ C0,
    const __nv_bfloat16* __restrict__ Ah1, const __nv_bfloat16* __restrict__ Al1,
    const __nv_bfloat16* __restrict__ Bh1, const __nv_bfloat16* __restrict__ Bl1,
    const float* __restrict__ b1, float* __restrict__ C1)
{
    extern __shared__ __align__(16) char dsm[];
    PDL_WAIT();
    if (blockIdx.z == 0)
        gemm_core(dsm, Ah0, Al0, Bh0, Bl0, b0, C0);
    else
        gemm_core(dsm, Ah1, Al1, Bh1, Bl1, b1, C1);
}

// ---------------------------------------------------------------------------
// Wavelet step — q and k in one launch; outputs to per-level pyramid slices
// ---------------------------------------------------------------------------
__global__ __launch_bounds__(256) void wavelet2_kernel(
    const float* __restrict__ xq, const float* __restrict__ xk,
    const float* __restrict__ ecd, const float* __restrict__ ecs,
    float* __restrict__ dq, float* __restrict__ qn,
    float* __restrict__ dk, float* __restrict__ kn, int Lh)
{
    __shared__ float wd[16][8], ws_[16][8];
    PDL_WAIT();
    int tid = threadIdx.x;
    if (tid < 128)       wd[tid >> 3][tid & 7] = ecd[tid];
    else if (tid < 256)  { int t = tid - 128; ws_[t >> 3][t & 7] = ecs[t]; }
    __syncthreads();

    const float* x = blockIdx.y ? xk : xq;
    float* od = blockIdx.y ? dk : dq;
    float* os = blockIdx.y ? kn : qn;

    long idx = (long)blockIdx.x * 256 + tid;
    long total = (long)BB * Lh * 64;
    if (idx >= total) return;
    int c = (int)(idx & 63);
    long bt = idx >> 6;
    int t2 = (int)(bt % Lh);
    int b = (int)(bt / Lh);

    const float* p0 = x + ((long)(b * 2 * Lh + 2 * t2)) * CKD + c * 8;
    float a[16];
    *(float4*)(a)      = *(const float4*)(p0);
    *(float4*)(a + 4)  = *(const float4*)(p0 + 4);
    *(float4*)(a + 8)  = *(const float4*)(p0 + CKD);
    *(float4*)(a + 12) = *(const float4*)(p0 + CKD + 4);

    float rd[8], rs[8];
#pragma unroll
    for (int kk = 0; kk < 8; kk++) { rd[kk] = 0.f; rs[kk] = 0.f; }
#pragma unroll
    for (int j = 0; j < 16; j++)
#pragma unroll
        for (int kk = 0; kk < 8; kk++) {
            rd[kk] += a[j] * wd[j][kk];
            rs[kk] += a[j] * ws_[j][kk];
        }
    float* pd = od + ((long)(b * Lh + t2)) * CKD + c * 8;
    float* ps = os + ((long)(b * Lh + t2)) * CKD + c * 8;
    *(float4*)(pd)     = *(float4*)(rd);
    *(float4*)(pd + 4) = *(float4*)(rd + 4);
    *(float4*)(ps)     = *(float4*)(rs);
    *(float4*)(ps + 4) = *(float4*)(rs + 4);
}

// ---------------------------------------------------------------------------
// Reconstruction step (optionally emits bf16 hi/lo split)
// ---------------------------------------------------------------------------
__global__ __launch_bounds__(256) void recon_kernel(
    const float* __restrict__ vin, const float* __restrict__ us,
    const float* __restrict__ ud, const float* __restrict__ rce,
    const float* __restrict__ rco, float* __restrict__ vout, int Lv,
    __nv_bfloat16* __restrict__ oh, __nv_bfloat16* __restrict__ ol,
    int do_split)
{
    __shared__ float we[16][8], wo[16][8];
    PDL_WAIT();
    int tid = threadIdx.x;
    if (tid < 128)       we[tid >> 3][tid & 7] = rce[tid];
    else if (tid < 256)  { int t = tid - 128; wo[t >> 3][t & 7] = rco[t]; }
    __syncthreads();

    long idx = (long)blockIdx.x * 256 + tid;
    long total = (long)BB * Lv * 64;
    if (idx >= total) return;
    int c = (int)(idx & 63);
    long bt = idx >> 6;
    int t = (int)(bt % Lv);
    int b = (int)(bt / Lv);

    long base = ((long)(b * Lv + t)) * CKD + c * 8;
    float a[16];
#pragma unroll
    for (int j = 0; j < 8; j++) a[j] = vin[base + j] + us[base + j];
    *(float4*)(a + 8)  = *(const float4*)(ud + base);
    *(float4*)(a + 12) = *(const float4*)(ud + base + 4);

    float re[8], ro[8];
#pragma unroll
    for (int kk = 0; kk < 8; kk++) { re[kk] = 0.f; ro[kk] = 0.f; }
#pragma unroll
    for (int j = 0; j < 16; j++)
#pragma unroll
        for (int kk = 0; kk < 8; kk++) {
            re[kk] += a[j] * we[j][kk];
            ro[kk] += a[j] * wo[j][kk];
        }
    long obase = ((long)(b * 2 * Lv + 2 * t)) * CKD + c * 8;
    float* pe = vout + obase;
    *(float4*)(pe)           = *(float4*)(re);
    *(float4*)(pe + 4)       = *(float4*)(re + 4);
    *(float4*)(pe + CKD)     = *(float4*)(ro);
    *(float4*)(pe + CKD + 4) = *(float4*)(ro + 4);

    if (do_split) {
        split_store4(oh, ol, (obase >> 2),           *(float4*)(re));
        split_store4(oh, ol, (obase >> 2) + 1,       *(float4*)(re + 4));
        split_store4(oh, ol, ((obase + CKD) >> 2),     *(float4*)(ro));
        split_store4(oh, ol, ((obase + CKD) >> 2) + 1, *(float4*)(ro + 4));
    }
}

// ---------------------------------------------------------------------------
// rfft_all: all 9 fca levels, 4 streams. grid (512, 9).
// bx: ec = bx&7, b = (bx>>3)&15, z = bx>>7. by = level.
// ---------------------------------------------------------------------------
__global__ __launch_bounds__(256) void rfft_all_kernel(
    const float* __restrict__ DQp, const float* __restrict__ DKp,
    const float* __restrict__ QSp, const float* __restrict__ KSp,
    float2* __restrict__ F0, float2* __restrict__ F1,
    float2* __restrict__ F2, float2* __restrict__ F3)
{
    __shared__ float2 tw[512];
    __shared__ float tile[64][64];
    PDL_WAIT();
    int tid = threadIdx.x;
    int bx = blockIdx.x;
    int lvl = blockIdx.y;
    int ec = bx & 7, b = (bx >> 3) & 15, z = bx >> 7;
    const int L = 1024 >> (lvl + 1);
    const int m = (L / 2 < 16) ? (L / 2) : 16;
    const long off = lvl_off(lvl);
    const long foff = (long)lvl * 131072;

    const float* x = (z == 0 ? DQp : (z == 1 ? DKp : (z == 2 ? QSp : KSp))) + off;
    float2* F = (z == 0 ? F0 : (z == 1 ? F1 : (z == 2 ? F2 : F3))) + foff;

    for (int i = tid; i < L; i += 256) {
        float th = 6.2831853071795864f * (float)i / (float)L;
        float s, c; sincosf(th, &s, &c);
        tw[i] = make_float2(c, s);
    }

    int eh = tid >> 2;
    int xg = tid & 3;
    float ar[4] = {0.f, 0.f, 0.f, 0.f}, ai[4] = {0.f, 0.f, 0.f, 0.f};

    for (int t0 = 0; t0 < L; t0 += 64) {
        int tc = L - t0 < 64 ? L - t0 : 64;
        __syncthreads();
        for (int i = tid; i < tc * 64; i += 256) {
            int tt = i >> 6, el = i & 63;
            tile[tt][el] = x[((long)(b * L + t0 + tt)) * CKD + ec * 64 + el];
        }
        __syncthreads();
        for (int tt = 0; tt < tc; tt++) {
            float v = tile[tt][eh];
            int t = t0 + tt;
#pragma unroll
            for (int j = 0; j < 4; j++) {
                int xx = xg + j * 4;
                int id = (xx * t) & (L - 1);
                float2 w = tw[id];
                ar[j] += v * w.x;
                ai[j] -= v * w.y;
            }
        }
    }
    int e = ec * 8 + (eh >> 3), h = eh & 7;
    float2* dst = F + ((long)((b * 8 + h) * 64 + e)) * 16;
#pragma unroll
    for (int j = 0; j < 4; j++) {
        int xx = xg + j * 4;
        if (xx < m) dst[xx] = make_float2(ar[j], ai[j]);
    }
}

// ---------------------------------------------------------------------------
// attn_all: all 9 levels x 2 pairs. grid (256, 9). bx: bh = bx&127, pair=bx>>7
// ---------------------------------------------------------------------------
__global__ __launch_bounds__(256) void attn_all_kernel(
    const float2* __restrict__ QFs, const float2* __restrict__ KFs,
    float2* __restrict__ OFs,
    const float2* __restrict__ QFd, const float2* __restrict__ KFd,
    float2* __restrict__ OFd)
{
    __shared__ float2 qf[1024], kf[1024], S[256];
    PDL_WAIT();
    int bh = blockIdx.x & 127, pair = blockIdx.x >> 7;
    int lvl = blockIdx.y;
    int tid = threadIdx.x;
    const int L = 1024 >> (lvl + 1);
    const int m = (L / 2 < 16) ? (L / 2) : 16;
    const long foff = (long)lvl * 131072;
    const float2* QF = (pair ? QFd : QFs) + foff;
    const float2* KF = (pair ? KFd : KFs) + foff;
    float2* OF = (pair ? OFd : OFs) + foff;
    const float2* qsrc = QF + (long)bh * 1024;
    const float2* ksrc = KF + (long)bh * 1024;
    for (int i = tid; i < 1024; i += 256) { qf[i] = qsrc[i]; kf[i] = ksrc[i]; }
    __syncthreads();

    for (int s = tid; s < m * m; s += 256) {
        int xx = s / m, yy = s - xx * m;
        float re = 0.f, im = 0.f;
#pragma unroll 8
        for (int e = 0; e < 64; e++) {
            float2 qv = qf[e * 16 + xx], kv = kf[e * 16 + yy];
            re += qv.x * kv.x - qv.y * kv.y;
            im += qv.x * kv.y + qv.y * kv.x;
        }
        float X = 2.f * re, Y = 2.f * im, orr, oii;
        if (fabsf(X) > 20.f) {
            orr = copysignf(1.f, X); oii = 0.f;
        } else {
            float ex = expf(X), enx = 1.f / ex;
            float sh = 0.5f * (ex - enx), ch = 0.5f * (ex + enx);
            float sy, cy; sincosf(Y, &sy, &cy);
            float den = ch + cy;
            orr = sh / den; oii = sy / den;
        }
        S[xx * 16 + yy] = make_float2(orr, oii);
    }
    __syncthreads();
    for (int o = tid; o < 64 * m; o += 256) {
        int e = o / m, xx = o - e * m;
        float re = 0.f, im = 0.f;
        for (int yy = 0; yy < m; yy++) {
            float2 sv = S[xx * 16 + yy], kv = kf[e * 16 + yy];
            re += sv.x * kv.x - sv.y * kv.y;
            im += sv.x * kv.y + sv.y * kv.x;
        }
        OF[(long)bh * 1024 + e * 16 + xx] = make_float2(re, im);
    }
}

// ---------------------------------------------------------------------------
// irfft_all: all 9 levels x 2 outputs. grid (256, 9).
// bx: ec = bx&7, b=(bx>>3)&15, z=bx>>7
// ---------------------------------------------------------------------------
__global__ __launch_bounds__(256) void irfft_all_kernel(
    const float2* __restrict__ OFs, const float2* __restrict__ OFd,
    float* __restrict__ USb, float* __restrict__ UDb)
{
    __shared__ float2 tw[512];
    __shared__ float2 of_s[64][16];
    PDL_WAIT();
    int tid = threadIdx.x;
    int bx = blockIdx.x, lvl = blockIdx.y;
    int ec = bx & 7, b = (bx >> 3) & 15, z = bx >> 7;
    const int L = 1024 >> (lvl + 1);
    const int m = (L / 2 < 16) ? (L / 2) : 16;
    const long off = lvl_off(lvl);
    const long foff = (long)lvl * 131072;
    float* out = (z ? UDb : USb) + off;
    const float2* ofs_g = OFs + foff;
    const float2* ofd_g = OFd + foff;

    for (int i = tid; i < L; i += 256) {
        float th = 6.2831853071795864f * (float)i / (float)L;
        float s, c; sincosf(th, &s, &c);
        tw[i] = make_float2(c, s);
    }
    float inv = 1.f / ((float)L * 4096.f);
    for (int i = tid; i < 1024; i += 256) {
        int el = i >> 4, xx = i & 15;
        int e = ec * 8 + (el >> 3), h = el & 7;
        float2 v = make_float2(0.f, 0.f);
        if (xx < m) {
            long src = ((long)((b * 8 + h) * 64 + e)) * 16 + xx;
            v = ofs_g[src];
            if (z) { float2 d = ofd_g[src]; v.x += d.x; v.y += d.y; }
        }
        float w = (xx == 0) ? inv : 2.f * inv;
        of_s[el][xx] = make_float2(v.x * w, v.y * w);
    }
    __syncthreads();

    const int el = tid & 63;
    float2 of[16];
#pragma unroll
    for (int xx = 0; xx < 16; xx++) of[xx] = of_s[el][xx];

    for (long i = tid; i < (long)L * 64; i += 256) {
        int t = (int)(i >> 6);
        float acc = 0.f;
#pragma unroll
        for (int xx = 0; xx < 16; xx++) {
            int id = (xx * t) & (L - 1);
            float2 w = tw[id];
            acc += of[xx].x * w.x - of[xx].y * w.y;
        }
        long dst = ((long)(b * L + t)) * CKD + ec * 64 + el;
        out[dst] = acc;
    }
}

__global__ void zero2_kernel(float* p0, float* p1, long n) {
    PDL_WAIT();
    long i = (long)blockIdx.x * blockDim.x + threadIdx.x;
    if (i < n) { p0[i] = 0.f; p1[i] = 0.f; }
}

// ---------------------------------------------------------------------------
// PDL launch helper
// ---------------------------------------------------------------------------
template <typename... Args>
static inline void pdl_launch(void (*kern)(Args...), dim3 g, dim3 b,
                              size_t smem, Args... args)
{
    cudaLaunchConfig_t cfg = {};
    cfg.gridDim = g;
    cfg.blockDim = b;
    cfg.dynamicSmemBytes = smem;
    cudaLaunchAttribute at[1];
    at[0].id = cudaLaunchAttributeProgrammaticStreamSerialization;
    at[0].val.programmaticStreamSerializationAllowed = 1;
    cfg.attrs = at;
    cfg.numAttrs = 1;
    cudaLaunchKernelEx(&cfg, kern, args...);
}

// ---------------------------------------------------------------------------
extern "C" void kernel_launch(void* const* d_in, const int* in_sizes, int n_in,
                              void* d_out, int out_size)
{
    const float* q    = (const float*)d_in[0];
    const float* k    = (const float*)d_in[1];
    const float* Lq_w = (const float*)d_in[3];
    const float* Lq_b = (const float*)d_in[4];
    const float* Lk_w = (const float*)d_in[5];
    const float* Lk_b = (const float*)d_in[6];
    const float* out_w = (const float*)d_in[9];
    const float* out_b = (const float*)d_in[10];
    const float* ec_s = (const float*)d_in[11];
    const float* ec_d = (const float*)d_in[12];
    const float* rc_e = (const float*)d_in[13];
    const float* rc_o = (const float*)d_in[14];

    float *QA, *KA, *QS, *KS, *DQp, *DKp, *US, *UD, *VA, *VB;
    float2 *QFs, *KFs, *QFd, *KFd, *OFs, *OFd;
    __nv_bfloat16 *Ah, *Al, *Ah2, *Al2, *Wh0, *Wl0, *Wh1, *Wl1, *Wh2, *Wl2;
    cudaGetSymbolAddress((void**)&QA, g_QA);
    cudaGetSymbolAddress((void**)&KA, g_KA);
    cudaGetSymbolAddress((void**)&QS, g_QS);
    cudaGetSymbolAddress((void**)&KS, g_KS);
    cudaGetSymbolAddress((void**)&DQp, g_DQp);
    cudaGetSymbolAddress((void**)&DKp, g_DKp);
    cudaGetSymbolAddress((void**)&US, g_US);
    cudaGetSymbolAddress((void**)&UD, g_UD);
    cudaGetSymbolAddress((void**)&VA, g_VA);
    cudaGetSymbolAddress((void**)&VB, g_VB);
    cudaGetSymbolAddress((void**)&QFs, g_QFs);
    cudaGetSymbolAddress((void**)&KFs, g_KFs);
    cudaGetSymbolAddress((void**)&QFd, g_QFd);
    cudaGetSymbolAddress((void**)&KFd, g_KFd);
    cudaGetSymbolAddress((void**)&OFs, g_OFs);
    cudaGetSymbolAddress((void**)&OFd, g_OFd);
    cudaGetSymbolAddress((void**)&Ah, g_Ah);
    cudaGetSymbolAddress((void**)&Al, g_Al);
    cudaGetSymbolAddress((void**)&Ah2, g_Ah2);
    cudaGetSymbolAddress((void**)&Al2, g_Al2);
    cudaGetSymbolAddress((void**)&Wh0, g_Wh0);
    cudaGetSymbolAddress((void**)&Wl0, g_Wl0);
    cudaGetSymbolAddress((void**)&Wh1, g_Wh1);
    cudaGetSymbolAddress((void**)&Wl1, g_Wl1);
    cudaGetSymbolAddress((void**)&Wh2, g_Wh2);
    cudaGetSymbolAddress((void**)&Wl2, g_Wl2);

    cudaFuncSetAttribute(gemm_bf16x3,
                         cudaFuncAttributeMaxDynamicSharedMemorySize,
                         GSMEM_BYTES);
    cudaFuncSetAttribute(gemm_bf16x3_dual,
                         cudaFuncAttributeMaxDynamicSharedMemorySize,
                         GSMEM_BYTES);

    // weight splits + input splits + dual projection GEMM
    pdl_launch(split_wt3_kernel, dim3(16, 16, 3), dim3(32, 8), 0,
               Lq_w, Lk_w, out_w, Wh0, Wl0, Wh1, Wl1, Wh2, Wl2);
    pdl_launch(split_a2_kernel, dim3(8192, 2), dim3(256), 0,
               q, k, Ah, Al, Ah2, Al2, (long)2097152);
    pdl_launch(gemm_bf16x3_dual, dim3(4, 128, 2), dim3(256), (size_t)GSMEM_BYTES,
               (const __nv_bfloat16*)Ah, (const __nv_bfloat16*)Al,
               (const __nv_bfloat16*)Wh0, (const __nv_bfloat16*)Wl0,
               Lq_b, QA,
               (const __nv_bfloat16*)Ah2, (const __nv_bfloat16*)Al2,
               (const __nv_bfloat16*)Wh1, (const __nv_bfloat16*)Wl1,
               Lk_b, KA);

    // wavelet chain: serial over 10 levels, outputs into per-level pyramids
    long offs[10]; int Lhs[10];
    {
        long off = 0;
        int L = 1024;
        for (int i = 0; i < 10; i++) {
            int Lh = L >> 1;
            Lhs[i] = Lh; offs[i] = off;
            off += (long)BB * Lh * CKD;
            const float* xq = (i == 0) ? QA : (QS + offs[i - 1]);
            const float* xk = (i == 0) ? KA : (KS + offs[i - 1]);
            long total = (long)BB * Lh * 64;
            int blocks = (int)((total + 255) / 256);
            pdl_launch(wavelet2_kernel, dim3(blocks, 2), dim3(256), 0,
                       xq, xk, ec_d, ec_s,
                       DQp + offs[i], QS + offs[i],
                       DKp + offs[i], KS + offs[i], Lh);
            L = Lh;
        }
    }

    // batched fca across levels 0..8
    pdl_launch(rfft_all_kernel, dim3(512, 9), dim3(256), 0,
               (const float*)DQp, (const float*)DKp,
               (const float*)QS, (const float*)KS,
               QFs, KFs, QFd, KFd);
    pdl_launch(attn_all_kernel, dim3(256, 9), dim3(256), 0,
               (const float2*)QFs, (const float2*)KFs, OFs,
               (const float2*)QFd, (const float2*)KFd, OFd);
    pdl_launch(irfft_all_kernel, dim3(256, 9), dim3(256), 0,
               (const float2*)OFs, (const float2*)OFd, US, UD);
    // level 9 (m=0): zero
    {
        long sz = (long)BB * Lhs[9] * CKD;
        pdl_launch(zero2_kernel, dim3((unsigned)((sz + 255) / 256)), dim3(256),
                   0, US + offs[9], UD + offs[9], sz);
    }

    pdl_launch(zero2_kernel, dim3(32), dim3(256), 0,
               VA, VA, (long)BB * 1 * CKD);
    float* vc = VA; float* vn = VB;
    for (int i = 9; i >= 0; i--) {
        int Lv = Lhs[i];
        long total = (long)BB * Lv * 64;
        pdl_launch(recon_kernel, dim3((unsigned)((total + 255) / 256)),
                   dim3(256), 0,
                   (const float*)vc, (const float*)(US + offs[i]),
                   (const float*)(UD + offs[i]), rc_e, rc_o, vn, Lv,
                   Ah, Al, (i == 0) ? 1 : 0);
        float* t = vc; vc = vn; vn = t;
    }

    // output projection (recon emitted the bf16 split into Ah/Al)
    pdl_launch(gemm_bf16x3, dim3(4, 128), dim3(256), (size_t)GSMEM_BYTES,
               (const __nv_bfloat16*)Ah, (const __nv_bfloat16*)Al,
               (const __nv_bfloat16*)Wh2, (const __nv_bfloat16*)Wl2,
               out_b, (float*)d_out);
}